// round 1
// baseline (speedup 1.0000x reference)
#include <cuda_runtime.h>
#include <math.h>

// Problem constants
#define BB 2
#define SS 4096
#define DD 1024
#define HH 16
#define HD 64
#define MM (BB * SS)   // 8192

// Scratch (device globals; allocation-free per harness rules)
__device__ float g_Q[MM * DD];
__device__ float g_K[MM * DD];
__device__ float g_V[MM * DD];
__device__ float g_A[MM * DD];

// ---------------------------------------------------------------------------
// Generic fp32 SGEMM: C = A[M,K] @ B[K,N] + bias[N]
// M=8192, N=1024, K=1024 fixed. Tile 128x128x16, 256 threads, 8x8 microtile.
// heads_layout == 0: C[m*N + n]
// heads_layout == 1: C[((b*H + h)*S + s)*HD + hd]  (b=m/S, s=m%S, h=n/HD, hd=n%HD)
// ---------------------------------------------------------------------------
__global__ void __launch_bounds__(256) sgemm_kernel(
    const float* __restrict__ A, const float* __restrict__ B,
    const float* __restrict__ bias, float* __restrict__ C, int heads_layout)
{
    const int Mi = 8192, Ni = 1024, Ki = 1024;
    (void)Mi;
    __shared__ float As[16][128];   // transposed A tile: As[k][m]
    __shared__ float Bs[16][128];   // Bs[k][n]

    const int tid = threadIdx.x;
    const int tx = tid & 15;        // 0..15 -> n group
    const int ty = tid >> 4;        // 0..15 -> m group
    const int bx = blockIdx.x;      // N tile (0..7)
    const int by = blockIdx.y;      // M tile (0..63)

    const float* Ap = A + (size_t)by * 128 * Ki;
    const float* Bp = B + bx * 128;

    const int arow = tid >> 2;      // 0..63
    const int ac4  = tid & 3;       // 0..3 (float4 along K)
    const int brow = tid >> 5;      // 0..7
    const int bc4  = tid & 31;      // 0..31 (float4 along N)

    float acc[8][8];
#pragma unroll
    for (int i = 0; i < 8; i++)
#pragma unroll
        for (int j = 0; j < 8; j++) acc[i][j] = 0.0f;

    for (int k0 = 0; k0 < Ki; k0 += 16) {
        // Load A tile (transposed into smem)
#pragma unroll
        for (int it = 0; it < 2; it++) {
            int r = arow + it * 64;
            float4 v = *(const float4*)(Ap + (size_t)r * Ki + k0 + ac4 * 4);
            As[ac4 * 4 + 0][r] = v.x;
            As[ac4 * 4 + 1][r] = v.y;
            As[ac4 * 4 + 2][r] = v.z;
            As[ac4 * 4 + 3][r] = v.w;
        }
        // Load B tile
#pragma unroll
        for (int it = 0; it < 2; it++) {
            int r = brow + it * 8;
            *(float4*)(&Bs[r][bc4 * 4]) =
                *(const float4*)(Bp + (size_t)(k0 + r) * Ni + bc4 * 4);
        }
        __syncthreads();

#pragma unroll
        for (int k = 0; k < 16; k++) {
            float ra[8], rb[8];
            *(float4*)&ra[0] = *(const float4*)&As[k][ty * 8];
            *(float4*)&ra[4] = *(const float4*)&As[k][ty * 8 + 4];
            *(float4*)&rb[0] = *(const float4*)&Bs[k][tx * 8];
            *(float4*)&rb[4] = *(const float4*)&Bs[k][tx * 8 + 4];
#pragma unroll
            for (int i = 0; i < 8; i++)
#pragma unroll
                for (int j = 0; j < 8; j++)
                    acc[i][j] = fmaf(ra[i], rb[j], acc[i][j]);
        }
        __syncthreads();
    }

    const int mbase = by * 128 + ty * 8;
    const int nbase = bx * 128 + tx * 8;

    if (heads_layout == 0) {
#pragma unroll
        for (int i = 0; i < 8; i++) {
            int m = mbase + i;
            float out[8];
#pragma unroll
            for (int j = 0; j < 8; j++) out[j] = acc[i][j] + bias[nbase + j];
            *(float4*)(C + (size_t)m * Ni + nbase)     = *(float4*)&out[0];
            *(float4*)(C + (size_t)m * Ni + nbase + 4) = *(float4*)&out[4];
        }
    } else {
        // heads layout: all 8 cols of this thread lie inside one head (nbase%64 <= 56)
        const int h  = nbase >> 6;
        const int hd = nbase & 63;
#pragma unroll
        for (int i = 0; i < 8; i++) {
            int m = mbase + i;
            int b = m >> 12;        // m / S
            int s = m & 4095;       // m % S
            float out[8];
#pragma unroll
            for (int j = 0; j < 8; j++) out[j] = acc[i][j] + bias[nbase + j];
            float* dst = C + ((size_t)(b * HH + h) * SS + s) * HD + hd;
            *(float4*)(dst)     = *(float4*)&out[0];
            *(float4*)(dst + 4) = *(float4*)&out[4];
        }
    }
}

// ---------------------------------------------------------------------------
// Flash attention, fp32. Q/K/V in [B,H,S,HD] layout (HD=64).
// Grid: (S/64, H, B); 256 threads; each thread owns a 4x4 microtile.
// Output written to [B,S,D] so the final projection reads row-major.
// ---------------------------------------------------------------------------
#define PAD 68   // row stride (floats) for 64-wide smem tiles; 16B-aligned rows

__global__ void __launch_bounds__(256) attn_kernel(
    const float* __restrict__ Qg, const float* __restrict__ Kg,
    const float* __restrict__ Vg, float* __restrict__ Og)
{
    extern __shared__ float sm[];
    float (*Qst)[PAD] = (float(*)[PAD])(sm);               // [d][q]  (transposed)
    float (*Kst)[PAD] = (float(*)[PAD])(sm + 64 * PAD);    // [d][kj] (transposed)
    float (*Vs )[PAD] = (float(*)[PAD])(sm + 2 * 64 * PAD);// [kj][dv]
    float (*Ps )[PAD] = (float(*)[PAD])(sm + 3 * 64 * PAD);// [q][kj]

    const int b = blockIdx.z, h = blockIdx.y;
    const int q0 = blockIdx.x * 64;
    const int bh = b * HH + h;
    const float* Qbh = Qg + (size_t)bh * SS * HD;
    const float* Kbh = Kg + (size_t)bh * SS * HD;
    const float* Vbh = Vg + (size_t)bh * SS * HD;

    const int tid = threadIdx.x;
    const int tx = tid & 15;   // k-col / dv group
    const int ty = tid >> 4;   // q-row group

    const int lrow = tid >> 2; // 0..63
    const int lc4  = tid & 3;  // 0..3

    const float scale = 0.125f;  // 1/sqrt(64)

    // Load Q tile transposed, scale folded in
#pragma unroll
    for (int it = 0; it < 4; it++) {
        int d = (lc4 + 4 * it) * 4;
        float4 v = *(const float4*)(Qbh + (size_t)(q0 + lrow) * HD + d);
        Qst[d + 0][lrow] = v.x * scale;
        Qst[d + 1][lrow] = v.y * scale;
        Qst[d + 2][lrow] = v.z * scale;
        Qst[d + 3][lrow] = v.w * scale;
    }

    float m[4], l[4], o[4][4];
#pragma unroll
    for (int i = 0; i < 4; i++) {
        m[i] = -1e30f; l[i] = 0.0f;
#pragma unroll
        for (int j = 0; j < 4; j++) o[i][j] = 0.0f;
    }

    for (int k0 = 0; k0 < SS; k0 += 64) {
        __syncthreads();  // previous PV done (and Qst ready on first iter)
        // Load K tile transposed + V tile natural
#pragma unroll
        for (int it = 0; it < 4; it++) {
            int d = (lc4 + 4 * it) * 4;
            float4 kv = *(const float4*)(Kbh + (size_t)(k0 + lrow) * HD + d);
            Kst[d + 0][lrow] = kv.x;
            Kst[d + 1][lrow] = kv.y;
            Kst[d + 2][lrow] = kv.z;
            Kst[d + 3][lrow] = kv.w;
            *(float4*)(&Vs[lrow][d]) =
                *(const float4*)(Vbh + (size_t)(k0 + lrow) * HD + d);
        }
        __syncthreads();

        // S = (Q*scale) @ K^T, 4x4 per thread
        float s[4][4];
#pragma unroll
        for (int i = 0; i < 4; i++)
#pragma unroll
            for (int j = 0; j < 4; j++) s[i][j] = 0.0f;

#pragma unroll 16
        for (int d = 0; d < 64; d++) {
            float4 qa = *(const float4*)(&Qst[d][ty * 4]);
            float4 kb = *(const float4*)(&Kst[d][tx * 4]);
            float ra[4] = {qa.x, qa.y, qa.z, qa.w};
            float rb[4] = {kb.x, kb.y, kb.z, kb.w};
#pragma unroll
            for (int i = 0; i < 4; i++)
#pragma unroll
                for (int j = 0; j < 4; j++)
                    s[i][j] = fmaf(ra[i], rb[j], s[i][j]);
        }

        // Online softmax: row reductions across the 16 tx lanes (same warp half)
        float rowmax[4];
#pragma unroll
        for (int i = 0; i < 4; i++) {
            float v = fmaxf(fmaxf(s[i][0], s[i][1]), fmaxf(s[i][2], s[i][3]));
#pragma unroll
            for (int off = 8; off >= 1; off >>= 1)
                v = fmaxf(v, __shfl_xor_sync(0xffffffffu, v, off));
            rowmax[i] = v;
        }

        float alpha[4];
#pragma unroll
        for (int i = 0; i < 4; i++) {
            float mnew = fmaxf(m[i], rowmax[i]);
            alpha[i] = __expf(m[i] - mnew);
            m[i] = mnew;
        }

        float rs[4] = {0.f, 0.f, 0.f, 0.f};
#pragma unroll
        for (int i = 0; i < 4; i++) {
            float prow[4];
#pragma unroll
            for (int j = 0; j < 4; j++) {
                float p = __expf(s[i][j] - m[i]);
                prow[j] = p;
                rs[i] += p;
            }
            *(float4*)(&Ps[ty * 4 + i][tx * 4]) = *(float4*)&prow[0];
        }
#pragma unroll
        for (int i = 0; i < 4; i++) {
#pragma unroll
            for (int off = 8; off >= 1; off >>= 1)
                rs[i] += __shfl_xor_sync(0xffffffffu, rs[i], off);
            l[i] = l[i] * alpha[i] + rs[i];
#pragma unroll
            for (int j = 0; j < 4; j++) o[i][j] *= alpha[i];
        }
        __syncthreads();  // Ps fully written

        // O += P @ V
#pragma unroll 16
        for (int kk = 0; kk < 64; kk++) {
            float pa[4];
#pragma unroll
            for (int i = 0; i < 4; i++) pa[i] = Ps[ty * 4 + i][kk];
            float4 vb = *(const float4*)(&Vs[kk][tx * 4]);
            float rb[4] = {vb.x, vb.y, vb.z, vb.w};
#pragma unroll
            for (int i = 0; i < 4; i++)
#pragma unroll
                for (int j = 0; j < 4; j++)
                    o[i][j] = fmaf(pa[i], rb[j], o[i][j]);
        }
    }

    // Epilogue: normalize and write [B,S,D] (d = h*64 + dv)
#pragma unroll
    for (int i = 0; i < 4; i++) {
        float inv = 1.0f / l[i];
        int q = q0 + ty * 4 + i;
        float out[4];
#pragma unroll
        for (int j = 0; j < 4; j++) out[j] = o[i][j] * inv;
        float* dst = Og + ((size_t)(b * SS + q)) * DD + h * 64 + tx * 4;
        *(float4*)dst = *(float4*)&out[0];
    }
}

// ---------------------------------------------------------------------------
// Launch
// ---------------------------------------------------------------------------
extern "C" void kernel_launch(void* const* d_in, const int* in_sizes, int n_in,
                              void* d_out, int out_size)
{
    (void)in_sizes; (void)n_in; (void)out_size;
    const float* X  = (const float*)d_in[0];
    const float* Wq = (const float*)d_in[1];
    const float* bq = (const float*)d_in[2];
    const float* Wk = (const float*)d_in[3];
    const float* bk = (const float*)d_in[4];
    const float* Wv = (const float*)d_in[5];
    const float* bv = (const float*)d_in[6];
    const float* Wo = (const float*)d_in[7];
    const float* bo = (const float*)d_in[8];
    float* out = (float*)d_out;

    float *pQ, *pK, *pV, *pA;
    cudaGetSymbolAddress((void**)&pQ, g_Q);
    cudaGetSymbolAddress((void**)&pK, g_K);
    cudaGetSymbolAddress((void**)&pV, g_V);
    cudaGetSymbolAddress((void**)&pA, g_A);

    const int smem_attn = 4 * 64 * PAD * sizeof(float);  // ~69.6 KB
    cudaFuncSetAttribute(attn_kernel,
                         cudaFuncAttributeMaxDynamicSharedMemorySize, smem_attn);

    dim3 gproj(DD / 128, MM / 128);   // 8 x 64
    sgemm_kernel<<<gproj, 256>>>(X, Wq, bq, pQ, 1);
    sgemm_kernel<<<gproj, 256>>>(X, Wk, bk, pK, 1);
    sgemm_kernel<<<gproj, 256>>>(X, Wv, bv, pV, 1);

    dim3 gattn(SS / 64, HH, BB);      // 64 x 16 x 2
    attn_kernel<<<gattn, 256, smem_attn>>>(pQ, pK, pV, pA);

    sgemm_kernel<<<gproj, 256>>>(pA, Wo, bo, out, 0);
}

// round 3
// speedup vs baseline: 1.2257x; 1.2257x over previous
#include <cuda_runtime.h>
#include <cuda_bf16.h>
#include <cstdint>
#include <math.h>

// Problem constants
#define BB 2
#define SS 4096
#define DD 1024
#define HH 16
#define HD 64
#define MM (BB * SS)   // 8192

// ---------------------------------------------------------------------------
// Scratch (device globals; allocation-free per harness rules)
// ---------------------------------------------------------------------------
__device__ float g_Q[MM * DD];
__device__ float g_K[MM * DD];
__device__ float g_V[MM * DD];
__device__ float g_A[MM * DD];
__device__ __nv_bfloat16 g_Xh[MM * DD];
__device__ __nv_bfloat16 g_Xl[MM * DD];
__device__ __nv_bfloat16 g_Wht[DD * DD];
__device__ __nv_bfloat16 g_Wlt[DD * DD];

// ---------------------------------------------------------------------------
// PTX helpers (portable sm_80+ features only: mma.sync / ldmatrix / cp.async)
// ---------------------------------------------------------------------------
__device__ __forceinline__ uint32_t smem_to_u32(const void* p) {
    uint32_t a;
    asm("{ .reg .u64 t; cvta.to.shared.u64 t, %1; cvt.u32.u64 %0, t; }"
        : "=r"(a) : "l"(p));
    return a;
}

__device__ __forceinline__ void cp_async16(uint32_t dst, const void* src) {
    asm volatile("cp.async.cg.shared.global [%0], [%1], 16;"
                 :: "r"(dst), "l"(src));
}
#define CP_COMMIT() asm volatile("cp.async.commit_group;" ::: "memory")
#define CP_WAIT1()  asm volatile("cp.async.wait_group 1;" ::: "memory")
#define CP_WAIT0()  asm volatile("cp.async.wait_group 0;" ::: "memory")

__device__ __forceinline__ void ldsm_x4(uint32_t& r0, uint32_t& r1,
                                        uint32_t& r2, uint32_t& r3, uint32_t addr) {
    asm volatile("ldmatrix.sync.aligned.m8n8.x4.shared.b16 {%0,%1,%2,%3}, [%4];"
                 : "=r"(r0), "=r"(r1), "=r"(r2), "=r"(r3) : "r"(addr));
}

__device__ __forceinline__ void mma16816(float* c, const uint32_t* a, const uint32_t* b) {
    asm volatile(
        "mma.sync.aligned.m16n8k16.row.col.f32.bf16.bf16.f32 "
        "{%0,%1,%2,%3}, {%4,%5,%6,%7}, {%8,%9}, {%0,%1,%2,%3};"
        : "+f"(c[0]), "+f"(c[1]), "+f"(c[2]), "+f"(c[3])
        : "r"(a[0]), "r"(a[1]), "r"(a[2]), "r"(a[3]), "r"(b[0]), "r"(b[1]));
}

// ---------------------------------------------------------------------------
// hi/lo bf16 split of X [M x 1024] (row-major, K contiguous)
// ---------------------------------------------------------------------------
__global__ void __launch_bounds__(256) xsplit_kernel(
    const float* __restrict__ X,
    __nv_bfloat16* __restrict__ Xh, __nv_bfloat16* __restrict__ Xl)
{
    int i = (blockIdx.x * 256 + threadIdx.x) * 4;
    float4 v = *(const float4*)(X + i);
    __nv_bfloat16 h0 = __float2bfloat16_rn(v.x);
    __nv_bfloat16 h1 = __float2bfloat16_rn(v.y);
    __nv_bfloat16 h2 = __float2bfloat16_rn(v.z);
    __nv_bfloat16 h3 = __float2bfloat16_rn(v.w);
    __nv_bfloat16 l0 = __float2bfloat16_rn(v.x - __bfloat162float(h0));
    __nv_bfloat16 l1 = __float2bfloat16_rn(v.y - __bfloat162float(h1));
    __nv_bfloat16 l2 = __float2bfloat16_rn(v.z - __bfloat162float(h2));
    __nv_bfloat16 l3 = __float2bfloat16_rn(v.w - __bfloat162float(h3));
    __nv_bfloat162 hp0; hp0.x = h0; hp0.y = h1;
    __nv_bfloat162 hp1; hp1.x = h2; hp1.y = h3;
    __nv_bfloat162 lp0; lp0.x = l0; lp0.y = l1;
    __nv_bfloat162 lp1; lp1.x = l2; lp1.y = l3;
    *(__nv_bfloat162*)(Xh + i)     = hp0;
    *(__nv_bfloat162*)(Xh + i + 2) = hp1;
    *(__nv_bfloat162*)(Xl + i)     = lp0;
    *(__nv_bfloat162*)(Xl + i + 2) = lp1;
}

// ---------------------------------------------------------------------------
// Transpose + split: W [K=1024, N=1024] fp32 -> Wt hi/lo [N, K] bf16
// ---------------------------------------------------------------------------
__global__ void __launch_bounds__(256) wsplit_kernel(
    const float* __restrict__ W,
    __nv_bfloat16* __restrict__ Wht, __nv_bfloat16* __restrict__ Wlt)
{
    __shared__ float t[32][33];
    int tx = threadIdx.x, ty = threadIdx.y;   // (32, 8)
    int n0 = blockIdx.x * 32, k0 = blockIdx.y * 32;
#pragma unroll
    for (int i = 0; i < 4; i++)
        t[ty + i * 8][tx] = W[(size_t)(k0 + ty + i * 8) * DD + n0 + tx];
    __syncthreads();
#pragma unroll
    for (int i = 0; i < 4; i++) {
        float v = t[tx][ty + i * 8];
        __nv_bfloat16 h = __float2bfloat16_rn(v);
        __nv_bfloat16 l = __float2bfloat16_rn(v - __bfloat162float(h));
        size_t idx = (size_t)(n0 + ty + i * 8) * DD + k0 + tx;
        Wht[idx] = h;
        Wlt[idx] = l;
    }
}

// ---------------------------------------------------------------------------
// HMMA (mma.sync) GEMM: C[8192,1024] = (Ah+Al) @ (Bh+Bl)^T + bias
//   3-term split product hh + hl + lh.
//   Tile 128x128; K chunks of 64; cp.async double buffered.
//   8 warps: warp grid 4(m) x 2(n), each warp 32x64 via m16n8k16 atoms.
// ---------------------------------------------------------------------------
#define KC 64
#define ASTRIDE 72                         // padded row stride (bf16 elems)
#define TILE_B (128 * ASTRIDE * 2)         // 18432 bytes per tile
#define BUF_B  (4 * TILE_B)                // Ah,Al,Bh,Bl per buffer
#define GEMM_SMEM (2 * BUF_B)              // 147456

__global__ void __launch_bounds__(256, 1) gemm_mma_kernel(
    const __nv_bfloat16* __restrict__ Ah_g,
    const __nv_bfloat16* __restrict__ Al_g,
    const __nv_bfloat16* __restrict__ Bh_g,
    const __nv_bfloat16* __restrict__ Bl_g,
    const float* __restrict__ bias,
    float* __restrict__ C, int heads_layout)
{
    extern __shared__ char smem[];
    const uint32_t smem_u = smem_to_u32(smem);

    const int tid = threadIdx.x;
    const int wid = tid >> 5;
    const int lane = tid & 31;
    const int mtile = blockIdx.y, ntile = blockIdx.x;

    const int wm = wid & 3;        // m slice (32 rows)
    const int wn = wid >> 2;       // n slice (64 cols)

    const __nv_bfloat16* srcs[4];
    srcs[0] = Ah_g + (size_t)mtile * 128 * DD;
    srcs[1] = Al_g + (size_t)mtile * 128 * DD;
    srcs[2] = Bh_g + (size_t)ntile * 128 * DD;
    srcs[3] = Bl_g + (size_t)ntile * 128 * DD;

    // ---- async staging of one K-chunk (4 tiles x 128 rows x 64 bf16) ----
    auto issue_chunk = [&](int c) {
        const uint32_t boff = smem_u + (uint32_t)(c & 1) * BUF_B;
#pragma unroll
        for (int i = 0; i < 16; i++) {
            int seg = tid + i * 256;          // 0..4095
            int t = seg >> 10;                // tile 0..3
            int rem = seg & 1023;
            int row = rem >> 3, g = rem & 7;
            uint32_t dst = boff + (uint32_t)t * TILE_B
                         + (uint32_t)(row * ASTRIDE + g * 8) * 2;
            cp_async16(dst, srcs[t] + (size_t)row * DD + c * KC + g * 8);
        }
    };

    float acc[2][8][4];
#pragma unroll
    for (int mi = 0; mi < 2; mi++)
#pragma unroll
        for (int ni = 0; ni < 8; ni++)
#pragma unroll
            for (int r = 0; r < 4; r++) acc[mi][ni][r] = 0.0f;

    // per-lane ldmatrix base offsets (within a tile, bytes)
    const int a_row = wm * 32 + (lane & 15);
    const int a_kof = (lane >> 4) * 8;
    const int b_row = wn * 64 + (lane & 7) + (lane >> 4) * 8;
    const int b_kof = ((lane >> 3) & 1) * 8;

    issue_chunk(0);
    CP_COMMIT();

    for (int c = 0; c < 16; c++) {
        if (c < 15) { issue_chunk(c + 1); CP_COMMIT(); CP_WAIT1(); }
        else        { CP_WAIT0(); }
        __syncthreads();

        const uint32_t boff = smem_u + (uint32_t)(c & 1) * BUF_B;
        const uint32_t tAh = boff;
        const uint32_t tAl = boff + TILE_B;
        const uint32_t tBh = boff + 2 * TILE_B;
        const uint32_t tBl = boff + 3 * TILE_B;

#pragma unroll
        for (int kb = 0; kb < KC; kb += 16) {
            uint32_t ah[2][4], al[2][4], bh[8][2], bl[8][2];
#pragma unroll
            for (int mi = 0; mi < 2; mi++) {
                uint32_t ao = (uint32_t)((a_row + mi * 16) * ASTRIDE + kb + a_kof) * 2;
                ldsm_x4(ah[mi][0], ah[mi][1], ah[mi][2], ah[mi][3], tAh + ao);
                ldsm_x4(al[mi][0], al[mi][1], al[mi][2], al[mi][3], tAl + ao);
            }
#pragma unroll
            for (int p = 0; p < 4; p++) {
                uint32_t bo = (uint32_t)((b_row + p * 16) * ASTRIDE + kb + b_kof) * 2;
                ldsm_x4(bh[2 * p][0], bh[2 * p][1], bh[2 * p + 1][0], bh[2 * p + 1][1], tBh + bo);
                ldsm_x4(bl[2 * p][0], bl[2 * p][1], bl[2 * p + 1][0], bl[2 * p + 1][1], tBl + bo);
            }
#pragma unroll
            for (int mi = 0; mi < 2; mi++)
#pragma unroll
                for (int ni = 0; ni < 8; ni++) {
                    mma16816(acc[mi][ni], ah[mi], bh[ni]);   // hh
                    mma16816(acc[mi][ni], ah[mi], bl[ni]);   // hl
                    mma16816(acc[mi][ni], al[mi], bh[ni]);   // lh
                }
        }
        __syncthreads();
    }

    // ---- epilogue: fragment c layout: c0,c1 at (m=lane/4, n=(lane%4)*2),
    //      c2,c3 at (m+8, same n) ----
    const int mb = mtile * 128 + wm * 32 + (lane >> 2);
    const int nb0 = ntile * 128 + wn * 64 + (lane & 3) * 2;

#pragma unroll
    for (int mi = 0; mi < 2; mi++) {
#pragma unroll
        for (int ni = 0; ni < 8; ni++) {
            int n = nb0 + ni * 8;
            float2 bsv = *(const float2*)(bias + n);
#pragma unroll
            for (int half = 0; half < 2; half++) {
                int m = mb + mi * 16 + half * 8;
                float2 o;
                o.x = acc[mi][ni][half * 2 + 0] + bsv.x;
                o.y = acc[mi][ni][half * 2 + 1] + bsv.y;
                float* dst;
                if (heads_layout == 0) {
                    dst = C + (size_t)m * DD + n;
                } else {
                    int h = n >> 6, hd = n & 63;
                    int bq = m >> 12, s = m & 4095;
                    dst = C + ((size_t)(bq * HH + h) * SS + s) * HD + hd;
                }
                *(float2*)dst = o;
            }
        }
    }
}

// ---------------------------------------------------------------------------
// Flash attention, fp32 (unchanged from round 1 — verified)
// ---------------------------------------------------------------------------
#define PAD 68

__global__ void __launch_bounds__(256) attn_kernel(
    const float* __restrict__ Qg, const float* __restrict__ Kg,
    const float* __restrict__ Vg, float* __restrict__ Og)
{
    extern __shared__ float sm[];
    float (*Qst)[PAD] = (float(*)[PAD])(sm);
    float (*Kst)[PAD] = (float(*)[PAD])(sm + 64 * PAD);
    float (*Vs )[PAD] = (float(*)[PAD])(sm + 2 * 64 * PAD);
    float (*Ps )[PAD] = (float(*)[PAD])(sm + 3 * 64 * PAD);

    const int b = blockIdx.z, h = blockIdx.y;
    const int q0 = blockIdx.x * 64;
    const int bh = b * HH + h;
    const float* Qbh = Qg + (size_t)bh * SS * HD;
    const float* Kbh = Kg + (size_t)bh * SS * HD;
    const float* Vbh = Vg + (size_t)bh * SS * HD;

    const int tid = threadIdx.x;
    const int tx = tid & 15;
    const int ty = tid >> 4;
    const int lrow = tid >> 2;
    const int lc4  = tid & 3;
    const float scale = 0.125f;

#pragma unroll
    for (int it = 0; it < 4; it++) {
        int d = (lc4 + 4 * it) * 4;
        float4 v = *(const float4*)(Qbh + (size_t)(q0 + lrow) * HD + d);
        Qst[d + 0][lrow] = v.x * scale;
        Qst[d + 1][lrow] = v.y * scale;
        Qst[d + 2][lrow] = v.z * scale;
        Qst[d + 3][lrow] = v.w * scale;
    }

    float m[4], l[4], o[4][4];
#pragma unroll
    for (int i = 0; i < 4; i++) {
        m[i] = -1e30f; l[i] = 0.0f;
#pragma unroll
        for (int j = 0; j < 4; j++) o[i][j] = 0.0f;
    }

    for (int k0 = 0; k0 < SS; k0 += 64) {
        __syncthreads();
#pragma unroll
        for (int it = 0; it < 4; it++) {
            int d = (lc4 + 4 * it) * 4;
            float4 kv = *(const float4*)(Kbh + (size_t)(k0 + lrow) * HD + d);
            Kst[d + 0][lrow] = kv.x;
            Kst[d + 1][lrow] = kv.y;
            Kst[d + 2][lrow] = kv.z;
            Kst[d + 3][lrow] = kv.w;
            *(float4*)(&Vs[lrow][d]) =
                *(const float4*)(Vbh + (size_t)(k0 + lrow) * HD + d);
        }
        __syncthreads();

        float s[4][4];
#pragma unroll
        for (int i = 0; i < 4; i++)
#pragma unroll
            for (int j = 0; j < 4; j++) s[i][j] = 0.0f;

#pragma unroll 16
        for (int d = 0; d < 64; d++) {
            float4 qa = *(const float4*)(&Qst[d][ty * 4]);
            float4 kb = *(const float4*)(&Kst[d][tx * 4]);
            float ra[4] = {qa.x, qa.y, qa.z, qa.w};
            float rb[4] = {kb.x, kb.y, kb.z, kb.w};
#pragma unroll
            for (int i = 0; i < 4; i++)
#pragma unroll
                for (int j = 0; j < 4; j++)
                    s[i][j] = fmaf(ra[i], rb[j], s[i][j]);
        }

        float rowmax[4];
#pragma unroll
        for (int i = 0; i < 4; i++) {
            float v = fmaxf(fmaxf(s[i][0], s[i][1]), fmaxf(s[i][2], s[i][3]));
#pragma unroll
            for (int off = 8; off >= 1; off >>= 1)
                v = fmaxf(v, __shfl_xor_sync(0xffffffffu, v, off));
            rowmax[i] = v;
        }

        float alpha[4];
#pragma unroll
        for (int i = 0; i < 4; i++) {
            float mnew = fmaxf(m[i], rowmax[i]);
            alpha[i] = __expf(m[i] - mnew);
            m[i] = mnew;
        }

        float rs[4] = {0.f, 0.f, 0.f, 0.f};
#pragma unroll
        for (int i = 0; i < 4; i++) {
            float prow[4];
#pragma unroll
            for (int j = 0; j < 4; j++) {
                float p = __expf(s[i][j] - m[i]);
                prow[j] = p;
                rs[i] += p;
            }
            *(float4*)(&Ps[ty * 4 + i][tx * 4]) = *(float4*)&prow[0];
        }
#pragma unroll
        for (int i = 0; i < 4; i++) {
#pragma unroll
            for (int off = 8; off >= 1; off >>= 1)
                rs[i] += __shfl_xor_sync(0xffffffffu, rs[i], off);
            l[i] = l[i] * alpha[i] + rs[i];
#pragma unroll
            for (int j = 0; j < 4; j++) o[i][j] *= alpha[i];
        }
        __syncthreads();

#pragma unroll 16
        for (int kk = 0; kk < 64; kk++) {
            float pa[4];
#pragma unroll
            for (int i = 0; i < 4; i++) pa[i] = Ps[ty * 4 + i][kk];
            float4 vb = *(const float4*)(&Vs[kk][tx * 4]);
            float rb[4] = {vb.x, vb.y, vb.z, vb.w};
#pragma unroll
            for (int i = 0; i < 4; i++)
#pragma unroll
                for (int j = 0; j < 4; j++)
                    o[i][j] = fmaf(pa[i], rb[j], o[i][j]);
        }
    }

#pragma unroll
    for (int i = 0; i < 4; i++) {
        float inv = 1.0f / l[i];
        int q = q0 + ty * 4 + i;
        float out[4];
#pragma unroll
        for (int j = 0; j < 4; j++) out[j] = o[i][j] * inv;
        float* dst = Og + ((size_t)(b * SS + q)) * DD + h * 64 + tx * 4;
        *(float4*)dst = *(float4*)&out[0];
    }
}

// ---------------------------------------------------------------------------
// Launch
// ---------------------------------------------------------------------------
extern "C" void kernel_launch(void* const* d_in, const int* in_sizes, int n_in,
                              void* d_out, int out_size)
{
    (void)in_sizes; (void)n_in; (void)out_size;
    const float* X  = (const float*)d_in[0];
    const float* Wq = (const float*)d_in[1];
    const float* bq = (const float*)d_in[2];
    const float* Wk = (const float*)d_in[3];
    const float* bk = (const float*)d_in[4];
    const float* Wv = (const float*)d_in[5];
    const float* bv = (const float*)d_in[6];
    const float* Wo = (const float*)d_in[7];
    const float* bo = (const float*)d_in[8];
    float* out = (float*)d_out;

    float *pQ, *pK, *pV, *pA;
    __nv_bfloat16 *pXh, *pXl, *pWht, *pWlt;
    cudaGetSymbolAddress((void**)&pQ, g_Q);
    cudaGetSymbolAddress((void**)&pK, g_K);
    cudaGetSymbolAddress((void**)&pV, g_V);
    cudaGetSymbolAddress((void**)&pA, g_A);
    cudaGetSymbolAddress((void**)&pXh, g_Xh);
    cudaGetSymbolAddress((void**)&pXl, g_Xl);
    cudaGetSymbolAddress((void**)&pWht, g_Wht);
    cudaGetSymbolAddress((void**)&pWlt, g_Wlt);

    const int smem_attn = 4 * 64 * PAD * sizeof(float);
    cudaFuncSetAttribute(attn_kernel,
                         cudaFuncAttributeMaxDynamicSharedMemorySize, smem_attn);
    cudaFuncSetAttribute(gemm_mma_kernel,
                         cudaFuncAttributeMaxDynamicSharedMemorySize, GEMM_SMEM);

    dim3 gW(32, 32), bW(32, 8);
    dim3 gG(DD / 128, MM / 128);   // (8, 64)

    // Split X once
    xsplit_kernel<<<MM * DD / 4 / 256, 256>>>(X, pXh, pXl);

    // Q, K, V projections (heads layout)
    wsplit_kernel<<<gW, bW>>>(Wq, pWht, pWlt);
    gemm_mma_kernel<<<gG, 256, GEMM_SMEM>>>(pXh, pXl, pWht, pWlt, bq, pQ, 1);
    wsplit_kernel<<<gW, bW>>>(Wk, pWht, pWlt);
    gemm_mma_kernel<<<gG, 256, GEMM_SMEM>>>(pXh, pXl, pWht, pWlt, bk, pK, 1);
    wsplit_kernel<<<gW, bW>>>(Wv, pWht, pWlt);
    gemm_mma_kernel<<<gG, 256, GEMM_SMEM>>>(pXh, pXl, pWht, pWlt, bv, pV, 1);

    // Attention
    dim3 gattn(SS / 64, HH, BB);
    attn_kernel<<<gattn, 256, smem_attn>>>(pQ, pK, pV, pA);

    // Output projection
    xsplit_kernel<<<MM * DD / 4 / 256, 256>>>(pA, pXh, pXl);
    wsplit_kernel<<<gW, bW>>>(Wo, pWht, pWlt);
    gemm_mma_kernel<<<gG, 256, GEMM_SMEM>>>(pXh, pXl, pWht, pWlt, bo, out, 0);
}

// round 4
// speedup vs baseline: 3.0311x; 2.4728x over previous
#include <cuda_runtime.h>
#include <cuda_bf16.h>
#include <cstdint>
#include <math.h>

// Problem constants
#define BB 2
#define SS 4096
#define DD 1024
#define HH 16
#define HD 64
#define MM (BB * SS)   // 8192

// ---------------------------------------------------------------------------
// Scratch (device globals; allocation-free per harness rules)
// ---------------------------------------------------------------------------
__device__ __nv_bfloat16 g_Xh[MM * DD];
__device__ __nv_bfloat16 g_Xl[MM * DD];
__device__ __nv_bfloat16 g_Wht[DD * DD];
__device__ __nv_bfloat16 g_Wlt[DD * DD];
__device__ __nv_bfloat16 g_Qh[MM * DD];
__device__ __nv_bfloat16 g_Ql[MM * DD];
__device__ __nv_bfloat16 g_Kh[MM * DD];
__device__ __nv_bfloat16 g_Kl[MM * DD];
__device__ __nv_bfloat16 g_Vh[MM * DD];
__device__ __nv_bfloat16 g_Vl[MM * DD];
__device__ __nv_bfloat16 g_Ah[MM * DD];
__device__ __nv_bfloat16 g_Al[MM * DD];

// ---------------------------------------------------------------------------
// PTX helpers (portable sm_80+ features only: mma.sync / ldmatrix / cp.async)
// ---------------------------------------------------------------------------
__device__ __forceinline__ uint32_t smem_to_u32(const void* p) {
    uint32_t a;
    asm("{ .reg .u64 t; cvta.to.shared.u64 t, %1; cvt.u32.u64 %0, t; }"
        : "=r"(a) : "l"(p));
    return a;
}

__device__ __forceinline__ void cp_async16(uint32_t dst, const void* src) {
    asm volatile("cp.async.cg.shared.global [%0], [%1], 16;"
                 :: "r"(dst), "l"(src));
}
#define CP_COMMIT() asm volatile("cp.async.commit_group;" ::: "memory")
#define CP_WAIT1()  asm volatile("cp.async.wait_group 1;" ::: "memory")
#define CP_WAIT0()  asm volatile("cp.async.wait_group 0;" ::: "memory")

__device__ __forceinline__ void ldsm_x4(uint32_t& r0, uint32_t& r1,
                                        uint32_t& r2, uint32_t& r3, uint32_t addr) {
    asm volatile("ldmatrix.sync.aligned.m8n8.x4.shared.b16 {%0,%1,%2,%3}, [%4];"
                 : "=r"(r0), "=r"(r1), "=r"(r2), "=r"(r3) : "r"(addr));
}

__device__ __forceinline__ void ldsm_x4t(uint32_t& r0, uint32_t& r1,
                                         uint32_t& r2, uint32_t& r3, uint32_t addr) {
    asm volatile("ldmatrix.sync.aligned.m8n8.x4.trans.shared.b16 {%0,%1,%2,%3}, [%4];"
                 : "=r"(r0), "=r"(r1), "=r"(r2), "=r"(r3) : "r"(addr));
}

__device__ __forceinline__ void mma16816(float* c, const uint32_t* a, const uint32_t* b) {
    asm volatile(
        "mma.sync.aligned.m16n8k16.row.col.f32.bf16.bf16.f32 "
        "{%0,%1,%2,%3}, {%4,%5,%6,%7}, {%8,%9}, {%0,%1,%2,%3};"
        : "+f"(c[0]), "+f"(c[1]), "+f"(c[2]), "+f"(c[3])
        : "r"(a[0]), "r"(a[1]), "r"(a[2]), "r"(a[3]), "r"(b[0]), "r"(b[1]));
}

// ---------------------------------------------------------------------------
// hi/lo bf16 split of X [M x 1024]
// ---------------------------------------------------------------------------
__global__ void __launch_bounds__(256) xsplit_kernel(
    const float* __restrict__ X,
    __nv_bfloat16* __restrict__ Xh, __nv_bfloat16* __restrict__ Xl)
{
    int i = (blockIdx.x * 256 + threadIdx.x) * 4;
    float4 v = *(const float4*)(X + i);
    __nv_bfloat162 hp0 = __floats2bfloat162_rn(v.x, v.y);
    __nv_bfloat162 hp1 = __floats2bfloat162_rn(v.z, v.w);
    __nv_bfloat162 lp0 = __floats2bfloat162_rn(v.x - __bfloat162float(hp0.x),
                                               v.y - __bfloat162float(hp0.y));
    __nv_bfloat162 lp1 = __floats2bfloat162_rn(v.z - __bfloat162float(hp1.x),
                                               v.w - __bfloat162float(hp1.y));
    *(__nv_bfloat162*)(Xh + i)     = hp0;
    *(__nv_bfloat162*)(Xh + i + 2) = hp1;
    *(__nv_bfloat162*)(Xl + i)     = lp0;
    *(__nv_bfloat162*)(Xl + i + 2) = lp1;
}

// ---------------------------------------------------------------------------
// Transpose + split: W [K=1024, N=1024] fp32 -> Wt hi/lo [N, K] bf16
// ---------------------------------------------------------------------------
__global__ void __launch_bounds__(256) wsplit_kernel(
    const float* __restrict__ W,
    __nv_bfloat16* __restrict__ Wht, __nv_bfloat16* __restrict__ Wlt)
{
    __shared__ float t[32][33];
    int tx = threadIdx.x, ty = threadIdx.y;   // (32, 8)
    int n0 = blockIdx.x * 32, k0 = blockIdx.y * 32;
#pragma unroll
    for (int i = 0; i < 4; i++)
        t[ty + i * 8][tx] = W[(size_t)(k0 + ty + i * 8) * DD + n0 + tx];
    __syncthreads();
#pragma unroll
    for (int i = 0; i < 4; i++) {
        float v = t[tx][ty + i * 8];
        __nv_bfloat16 h = __float2bfloat16_rn(v);
        __nv_bfloat16 l = __float2bfloat16_rn(v - __bfloat162float(h));
        size_t idx = (size_t)(n0 + ty + i * 8) * DD + k0 + tx;
        Wht[idx] = h;
        Wlt[idx] = l;
    }
}

// ---------------------------------------------------------------------------
// HMMA GEMM: C = (Ah+Al)[8192,1024] @ (Bh+Bl)^T + bias
//   mode 0: fp32 row-major to Cf
//   mode 1: (acc+bias)*scale split into bf16 hi/lo, heads layout [B,H,S,HD]
// ---------------------------------------------------------------------------
#define KC 64
#define ASTRIDE 72
#define TILE_B (128 * ASTRIDE * 2)
#define BUF_B  (4 * TILE_B)
#define GEMM_SMEM (2 * BUF_B)

__global__ void __launch_bounds__(256, 1) gemm_mma_kernel(
    const __nv_bfloat16* __restrict__ Ah_g,
    const __nv_bfloat16* __restrict__ Al_g,
    const __nv_bfloat16* __restrict__ Bh_g,
    const __nv_bfloat16* __restrict__ Bl_g,
    const float* __restrict__ bias,
    float* __restrict__ Cf,
    __nv_bfloat16* __restrict__ Ch, __nv_bfloat16* __restrict__ Cl,
    float scale, int mode)
{
    extern __shared__ char smem[];
    const uint32_t smem_u = smem_to_u32(smem);

    const int tid = threadIdx.x;
    const int wid = tid >> 5;
    const int lane = tid & 31;
    const int mtile = blockIdx.y, ntile = blockIdx.x;

    const int wm = wid & 3;
    const int wn = wid >> 2;

    const __nv_bfloat16* srcs[4];
    srcs[0] = Ah_g + (size_t)mtile * 128 * DD;
    srcs[1] = Al_g + (size_t)mtile * 128 * DD;
    srcs[2] = Bh_g + (size_t)ntile * 128 * DD;
    srcs[3] = Bl_g + (size_t)ntile * 128 * DD;

    auto issue_chunk = [&](int c) {
        const uint32_t boff = smem_u + (uint32_t)(c & 1) * BUF_B;
#pragma unroll
        for (int i = 0; i < 16; i++) {
            int seg = tid + i * 256;
            int t = seg >> 10;
            int rem = seg & 1023;
            int row = rem >> 3, g = rem & 7;
            uint32_t dst = boff + (uint32_t)t * TILE_B
                         + (uint32_t)(row * ASTRIDE + g * 8) * 2;
            cp_async16(dst, srcs[t] + (size_t)row * DD + c * KC + g * 8);
        }
    };

    float acc[2][8][4];
#pragma unroll
    for (int mi = 0; mi < 2; mi++)
#pragma unroll
        for (int ni = 0; ni < 8; ni++)
#pragma unroll
            for (int r = 0; r < 4; r++) acc[mi][ni][r] = 0.0f;

    const int a_row = wm * 32 + (lane & 15);
    const int a_kof = (lane >> 4) * 8;
    const int b_row = wn * 64 + (lane & 7) + (lane >> 4) * 8;
    const int b_kof = ((lane >> 3) & 1) * 8;

    issue_chunk(0);
    CP_COMMIT();

    for (int c = 0; c < 16; c++) {
        if (c < 15) { issue_chunk(c + 1); CP_COMMIT(); CP_WAIT1(); }
        else        { CP_WAIT0(); }
        __syncthreads();

        const uint32_t boff = smem_u + (uint32_t)(c & 1) * BUF_B;
        const uint32_t tAh = boff;
        const uint32_t tAl = boff + TILE_B;
        const uint32_t tBh = boff + 2 * TILE_B;
        const uint32_t tBl = boff + 3 * TILE_B;

#pragma unroll
        for (int kb = 0; kb < KC; kb += 16) {
            uint32_t ah[2][4], al[2][4], bh[8][2], bl[8][2];
#pragma unroll
            for (int mi = 0; mi < 2; mi++) {
                uint32_t ao = (uint32_t)((a_row + mi * 16) * ASTRIDE + kb + a_kof) * 2;
                ldsm_x4(ah[mi][0], ah[mi][1], ah[mi][2], ah[mi][3], tAh + ao);
                ldsm_x4(al[mi][0], al[mi][1], al[mi][2], al[mi][3], tAl + ao);
            }
#pragma unroll
            for (int p = 0; p < 4; p++) {
                uint32_t bo = (uint32_t)((b_row + p * 16) * ASTRIDE + kb + b_kof) * 2;
                ldsm_x4(bh[2 * p][0], bh[2 * p][1], bh[2 * p + 1][0], bh[2 * p + 1][1], tBh + bo);
                ldsm_x4(bl[2 * p][0], bl[2 * p][1], bl[2 * p + 1][0], bl[2 * p + 1][1], tBl + bo);
            }
#pragma unroll
            for (int mi = 0; mi < 2; mi++)
#pragma unroll
                for (int ni = 0; ni < 8; ni++) {
                    mma16816(acc[mi][ni], ah[mi], bh[ni]);
                    mma16816(acc[mi][ni], ah[mi], bl[ni]);
                    mma16816(acc[mi][ni], al[mi], bh[ni]);
                }
        }
        __syncthreads();
    }

    const int mb = mtile * 128 + wm * 32 + (lane >> 2);
    const int nb0 = ntile * 128 + wn * 64 + (lane & 3) * 2;

    if (mode == 0) {
#pragma unroll
        for (int mi = 0; mi < 2; mi++)
#pragma unroll
            for (int ni = 0; ni < 8; ni++) {
                int n = nb0 + ni * 8;
                float2 bsv = *(const float2*)(bias + n);
#pragma unroll
                for (int half = 0; half < 2; half++) {
                    int m = mb + mi * 16 + half * 8;
                    float2 o;
                    o.x = acc[mi][ni][half * 2 + 0] + bsv.x;
                    o.y = acc[mi][ni][half * 2 + 1] + bsv.y;
                    *(float2*)(Cf + (size_t)m * DD + n) = o;
                }
            }
    } else {
#pragma unroll
        for (int mi = 0; mi < 2; mi++)
#pragma unroll
            for (int ni = 0; ni < 8; ni++) {
                int n = nb0 + ni * 8;
                float2 bsv = *(const float2*)(bias + n);
                int hh2 = n >> 6, hd = n & 63;
#pragma unroll
                for (int half = 0; half < 2; half++) {
                    int mg = mb + mi * 16 + half * 8;
                    float v0 = (acc[mi][ni][half * 2 + 0] + bsv.x) * scale;
                    float v1 = (acc[mi][ni][half * 2 + 1] + bsv.y) * scale;
                    __nv_bfloat162 hp = __floats2bfloat162_rn(v0, v1);
                    __nv_bfloat162 lp = __floats2bfloat162_rn(
                        v0 - __bfloat162float(hp.x), v1 - __bfloat162float(hp.y));
                    int bq = mg >> 12, sseq = mg & 4095;
                    size_t off = ((size_t)(bq * HH + hh2) * SS + sseq) * HD + hd;
                    *(__nv_bfloat162*)(Ch + off) = hp;
                    *(__nv_bfloat162*)(Cl + off) = lp;
                }
            }
    }
}

// ---------------------------------------------------------------------------
// Flash attention with mma.sync bf16 hi/lo splits.
//   CTA: 128 q rows of one (b,h); 8 warps x 16 rows. K/V tiles of 64 keys,
//   cp.async double-buffered. QK: 3-term split; PV: 3-term split.
//   Epilogue writes bf16 hi/lo A directly in row-major [M, D].
// ---------------------------------------------------------------------------
#define TQ 128
#define TK 64
#define QST 72
#define QTILE_B (128 * QST * 2)   // 18432
#define KTILE_B (64 * QST * 2)    // 9216
#define ATTN_SMEM (2 * QTILE_B + 2 * 4 * KTILE_B)  // 110592

__global__ void __launch_bounds__(256, 1) attn_mma_kernel(
    const __nv_bfloat16* __restrict__ Qh_g, const __nv_bfloat16* __restrict__ Ql_g,
    const __nv_bfloat16* __restrict__ Kh_g, const __nv_bfloat16* __restrict__ Kl_g,
    const __nv_bfloat16* __restrict__ Vh_g, const __nv_bfloat16* __restrict__ Vl_g,
    __nv_bfloat16* __restrict__ Ah, __nv_bfloat16* __restrict__ Al)
{
    extern __shared__ char smem[];
    const uint32_t smem_u = smem_to_u32(smem);
    const uint32_t sQh = smem_u;
    const uint32_t sQl = smem_u + QTILE_B;
    const uint32_t sBuf = smem_u + 2 * QTILE_B;

    const int tid = threadIdx.x, wid = tid >> 5, lane = tid & 31;
    const int b = blockIdx.z, h = blockIdx.y;
    const int q0 = blockIdx.x * TQ;
    const size_t bhoff = (size_t)(b * HH + h) * SS * HD;

    // Stage Q (hi + lo)
    {
        const __nv_bfloat16* qsrc[2] = { Qh_g + bhoff + (size_t)q0 * HD,
                                         Ql_g + bhoff + (size_t)q0 * HD };
#pragma unroll
        for (int i = 0; i < 8; i++) {
            int seg = tid + i * 256;
            int arr = seg >> 10, rem = seg & 1023;
            int row = rem >> 3, g = rem & 7;
            cp_async16(smem_u + (uint32_t)arr * QTILE_B + (uint32_t)(row * QST + g * 8) * 2,
                       qsrc[arr] + (size_t)row * HD + g * 8);
        }
    }
    CP_COMMIT();

    const __nv_bfloat16* kvsrc[4] = { Kh_g + bhoff, Kl_g + bhoff,
                                      Vh_g + bhoff, Vl_g + bhoff };
    auto issue_kv = [&](int t) {
        const uint32_t boff = sBuf + (uint32_t)(t & 1) * (4 * KTILE_B);
#pragma unroll
        for (int i = 0; i < 8; i++) {
            int seg = tid + i * 256;
            int arr = seg >> 9;        // 0..3
            int rem = seg & 511;
            int row = rem >> 3, g = rem & 7;
            cp_async16(boff + (uint32_t)arr * KTILE_B + (uint32_t)(row * QST + g * 8) * 2,
                       kvsrc[arr] + (size_t)(t * TK + row) * HD + g * 8);
        }
    };
    issue_kv(0); CP_COMMIT();

    CP_WAIT1();        // Q staged (tile-0 group may still be in flight)
    __syncthreads();

    // Q fragments (held in registers for the whole kernel)
    uint32_t qh[4][4], ql[4][4];
    {
        const int a_row = wid * 16 + (lane & 15);
        const int a_kof = (lane >> 4) * 8;
#pragma unroll
        for (int k = 0; k < 4; k++) {
            uint32_t ao = (uint32_t)(a_row * QST + k * 16 + a_kof) * 2;
            ldsm_x4(qh[k][0], qh[k][1], qh[k][2], qh[k][3], sQh + ao);
            ldsm_x4(ql[k][0], ql[k][1], ql[k][2], ql[k][3], sQl + ao);
        }
    }

    float m0 = -1e30f, m1 = -1e30f, l0 = 0.0f, l1 = 0.0f;
    float o[8][4];
#pragma unroll
    for (int nb = 0; nb < 8; nb++)
#pragma unroll
        for (int r = 0; r < 4; r++) o[nb][r] = 0.0f;

    const int b_row = (lane & 7) + (lane >> 4) * 8;   // K B-frag row within 16-group
    const int b_kof = ((lane >> 3) & 1) * 8;
    const int v_row = (lane & 15);                    // V trans-frag row
    const int v_col = (lane >> 4) * 8;

    for (int t = 0; t < SS / TK; t++) {
        if (t < SS / TK - 1) { issue_kv(t + 1); CP_COMMIT(); CP_WAIT1(); }
        else                 { CP_WAIT0(); }
        __syncthreads();

        const uint32_t boff = sBuf + (uint32_t)(t & 1) * (4 * KTILE_B);
        const uint32_t tKh = boff, tKl = boff + KTILE_B;
        const uint32_t tVh = boff + 2 * KTILE_B, tVl = boff + 3 * KTILE_B;

        // ---- S = Q K^T (3-term split) ----
        float s[8][4];
#pragma unroll
        for (int nb = 0; nb < 8; nb++)
#pragma unroll
            for (int r = 0; r < 4; r++) s[nb][r] = 0.0f;

#pragma unroll
        for (int k = 0; k < 4; k++) {
            uint32_t kh[8][2], kl[8][2];
#pragma unroll
            for (int p = 0; p < 4; p++) {
                uint32_t bo = (uint32_t)((p * 16 + b_row) * QST + k * 16 + b_kof) * 2;
                ldsm_x4(kh[2 * p][0], kh[2 * p][1], kh[2 * p + 1][0], kh[2 * p + 1][1], tKh + bo);
                ldsm_x4(kl[2 * p][0], kl[2 * p][1], kl[2 * p + 1][0], kl[2 * p + 1][1], tKl + bo);
            }
#pragma unroll
            for (int nb = 0; nb < 8; nb++) {
                mma16816(s[nb], qh[k], kh[nb]);
                mma16816(s[nb], qh[k], kl[nb]);
                mma16816(s[nb], ql[k], kh[nb]);
            }
        }

        // ---- online softmax ----
        float rm0 = -1e30f, rm1 = -1e30f;
#pragma unroll
        for (int nb = 0; nb < 8; nb++) {
            rm0 = fmaxf(rm0, fmaxf(s[nb][0], s[nb][1]));
            rm1 = fmaxf(rm1, fmaxf(s[nb][2], s[nb][3]));
        }
        rm0 = fmaxf(rm0, __shfl_xor_sync(0xffffffffu, rm0, 1));
        rm0 = fmaxf(rm0, __shfl_xor_sync(0xffffffffu, rm0, 2));
        rm1 = fmaxf(rm1, __shfl_xor_sync(0xffffffffu, rm1, 1));
        rm1 = fmaxf(rm1, __shfl_xor_sync(0xffffffffu, rm1, 2));

        float mn0 = fmaxf(m0, rm0), mn1 = fmaxf(m1, rm1);
        float al0 = __expf(m0 - mn0), al1 = __expf(m1 - mn1);
        m0 = mn0; m1 = mn1;

        float rs0 = 0.0f, rs1 = 0.0f;
#pragma unroll
        for (int nb = 0; nb < 8; nb++) {
            s[nb][0] = __expf(s[nb][0] - mn0);
            s[nb][1] = __expf(s[nb][1] - mn0);
            s[nb][2] = __expf(s[nb][2] - mn1);
            s[nb][3] = __expf(s[nb][3] - mn1);
            rs0 += s[nb][0] + s[nb][1];
            rs1 += s[nb][2] + s[nb][3];
        }
        rs0 += __shfl_xor_sync(0xffffffffu, rs0, 1);
        rs0 += __shfl_xor_sync(0xffffffffu, rs0, 2);
        rs1 += __shfl_xor_sync(0xffffffffu, rs1, 1);
        rs1 += __shfl_xor_sync(0xffffffffu, rs1, 2);
        l0 = l0 * al0 + rs0;
        l1 = l1 * al1 + rs1;
#pragma unroll
        for (int nb = 0; nb < 8; nb++) {
            o[nb][0] *= al0; o[nb][1] *= al0;
            o[nb][2] *= al1; o[nb][3] *= al1;
        }

        // ---- pack P into A-operand fragments (hi + lo) ----
        uint32_t ph[4][4], pl[4][4];
#pragma unroll
        for (int j = 0; j < 4; j++) {
            float pv[4][2] = {
                { s[2 * j][0],     s[2 * j][1]     },
                { s[2 * j][2],     s[2 * j][3]     },
                { s[2 * j + 1][0], s[2 * j + 1][1] },
                { s[2 * j + 1][2], s[2 * j + 1][3] } };
#pragma unroll
            for (int r = 0; r < 4; r++) {
                __nv_bfloat162 hp = __floats2bfloat162_rn(pv[r][0], pv[r][1]);
                __nv_bfloat162 lp = __floats2bfloat162_rn(
                    pv[r][0] - __bfloat162float(hp.x),
                    pv[r][1] - __bfloat162float(hp.y));
                ph[j][r] = *reinterpret_cast<uint32_t*>(&hp);
                pl[j][r] = *reinterpret_cast<uint32_t*>(&lp);
            }
        }

        // ---- O += P V (3-term split) ----
#pragma unroll
        for (int j = 0; j < 4; j++) {
            uint32_t vh[8][2], vl[8][2];
#pragma unroll
            for (int p = 0; p < 4; p++) {
                uint32_t vo = (uint32_t)((j * 16 + v_row) * QST + p * 16 + v_col) * 2;
                ldsm_x4t(vh[2 * p][0], vh[2 * p][1], vh[2 * p + 1][0], vh[2 * p + 1][1], tVh + vo);
                ldsm_x4t(vl[2 * p][0], vl[2 * p][1], vl[2 * p + 1][0], vl[2 * p + 1][1], tVl + vo);
            }
#pragma unroll
            for (int nb = 0; nb < 8; nb++) {
                mma16816(o[nb], ph[j], vh[nb]);
                mma16816(o[nb], ph[j], vl[nb]);
                mma16816(o[nb], pl[j], vh[nb]);
            }
        }
        __syncthreads();
    }

    // ---- epilogue: normalize, split hi/lo, write row-major [M, D] ----
    const float inv0 = 1.0f / l0, inv1 = 1.0f / l1;
    const int qrow = q0 + wid * 16 + (lane >> 2);
    const size_t mrow0 = (size_t)(b * SS + qrow);
    const size_t mrow1 = mrow0 + 8;
    const int colb = h * HD + (lane & 3) * 2;
#pragma unroll
    for (int nb = 0; nb < 8; nb++) {
        int col = colb + nb * 8;
        float x0 = o[nb][0] * inv0, x1 = o[nb][1] * inv0;
        float x2 = o[nb][2] * inv1, x3 = o[nb][3] * inv1;
        __nv_bfloat162 h0 = __floats2bfloat162_rn(x0, x1);
        __nv_bfloat162 g0 = __floats2bfloat162_rn(
            x0 - __bfloat162float(h0.x), x1 - __bfloat162float(h0.y));
        __nv_bfloat162 h1 = __floats2bfloat162_rn(x2, x3);
        __nv_bfloat162 g1 = __floats2bfloat162_rn(
            x2 - __bfloat162float(h1.x), x3 - __bfloat162float(h1.y));
        *(__nv_bfloat162*)(Ah + mrow0 * DD + col) = h0;
        *(__nv_bfloat162*)(Al + mrow0 * DD + col) = g0;
        *(__nv_bfloat162*)(Ah + mrow1 * DD + col) = h1;
        *(__nv_bfloat162*)(Al + mrow1 * DD + col) = g1;
    }
}

// ---------------------------------------------------------------------------
// Launch
// ---------------------------------------------------------------------------
extern "C" void kernel_launch(void* const* d_in, const int* in_sizes, int n_in,
                              void* d_out, int out_size)
{
    (void)in_sizes; (void)n_in; (void)out_size;
    const float* X  = (const float*)d_in[0];
    const float* Wq = (const float*)d_in[1];
    const float* bq = (const float*)d_in[2];
    const float* Wk = (const float*)d_in[3];
    const float* bk = (const float*)d_in[4];
    const float* Wv = (const float*)d_in[5];
    const float* bv = (const float*)d_in[6];
    const float* Wo = (const float*)d_in[7];
    const float* bo = (const float*)d_in[8];
    float* out = (float*)d_out;

    __nv_bfloat16 *pXh, *pXl, *pWht, *pWlt;
    __nv_bfloat16 *pQh, *pQl, *pKh, *pKl, *pVh, *pVl, *pAh, *pAl;
    cudaGetSymbolAddress((void**)&pXh, g_Xh);
    cudaGetSymbolAddress((void**)&pXl, g_Xl);
    cudaGetSymbolAddress((void**)&pWht, g_Wht);
    cudaGetSymbolAddress((void**)&pWlt, g_Wlt);
    cudaGetSymbolAddress((void**)&pQh, g_Qh);
    cudaGetSymbolAddress((void**)&pQl, g_Ql);
    cudaGetSymbolAddress((void**)&pKh, g_Kh);
    cudaGetSymbolAddress((void**)&pKl, g_Kl);
    cudaGetSymbolAddress((void**)&pVh, g_Vh);
    cudaGetSymbolAddress((void**)&pVl, g_Vl);
    cudaGetSymbolAddress((void**)&pAh, g_Ah);
    cudaGetSymbolAddress((void**)&pAl, g_Al);

    cudaFuncSetAttribute(gemm_mma_kernel,
                         cudaFuncAttributeMaxDynamicSharedMemorySize, GEMM_SMEM);
    cudaFuncSetAttribute(attn_mma_kernel,
                         cudaFuncAttributeMaxDynamicSharedMemorySize, ATTN_SMEM);

    dim3 gW(32, 32), bW(32, 8);
    dim3 gG(DD / 128, MM / 128);

    xsplit_kernel<<<MM * DD / 4 / 256, 256>>>(X, pXh, pXl);

    // Q projection (scale 1/8 folded), K, V projections -> bf16 hi/lo heads layout
    wsplit_kernel<<<gW, bW>>>(Wq, pWht, pWlt);
    gemm_mma_kernel<<<gG, 256, GEMM_SMEM>>>(pXh, pXl, pWht, pWlt, bq,
                                            nullptr, pQh, pQl, 0.125f, 1);
    wsplit_kernel<<<gW, bW>>>(Wk, pWht, pWlt);
    gemm_mma_kernel<<<gG, 256, GEMM_SMEM>>>(pXh, pXl, pWht, pWlt, bk,
                                            nullptr, pKh, pKl, 1.0f, 1);
    wsplit_kernel<<<gW, bW>>>(Wv, pWht, pWlt);
    gemm_mma_kernel<<<gG, 256, GEMM_SMEM>>>(pXh, pXl, pWht, pWlt, bv,
                                            nullptr, pVh, pVl, 1.0f, 1);

    // Attention -> bf16 hi/lo A (row-major [M, D])
    dim3 gattn(SS / TQ, HH, BB);   // (32, 16, 2)
    attn_mma_kernel<<<gattn, 256, ATTN_SMEM>>>(pQh, pQl, pKh, pKl, pVh, pVl,
                                               pAh, pAl);

    // Output projection (fp32 out)
    wsplit_kernel<<<gW, bW>>>(Wo, pWht, pWlt);
    gemm_mma_kernel<<<gG, 256, GEMM_SMEM>>>(pAh, pAl, pWht, pWlt, bo,
                                            out, nullptr, nullptr, 1.0f, 0);
}

// round 5
// speedup vs baseline: 3.0662x; 1.0116x over previous
#include <cuda_runtime.h>
#include <cuda_bf16.h>
#include <cstdint>
#include <math.h>

// Problem constants
#define BB 2
#define SS 4096
#define DD 1024
#define HH 16
#define HD 64
#define MM (BB * SS)   // 8192

// ---------------------------------------------------------------------------
// Scratch (device globals; allocation-free per harness rules)
// ---------------------------------------------------------------------------
__device__ __nv_bfloat16 g_Xh[MM * DD];
__device__ __nv_bfloat16 g_Xl[MM * DD];
__device__ __nv_bfloat16 g_Wht[4 * DD * DD];   // Wq,Wk,Wv,Wo transposed hi
__device__ __nv_bfloat16 g_Wlt[4 * DD * DD];   // lo
__device__ __nv_bfloat16 g_Qh[MM * DD];
__device__ __nv_bfloat16 g_Ql[MM * DD];
__device__ __nv_bfloat16 g_Kh[MM * DD];
__device__ __nv_bfloat16 g_Kl[MM * DD];
__device__ __nv_bfloat16 g_Vh[MM * DD];
__device__ __nv_bfloat16 g_Vl[MM * DD];
__device__ __nv_bfloat16 g_Ah[MM * DD];
__device__ __nv_bfloat16 g_Al[MM * DD];

// ---------------------------------------------------------------------------
// PTX helpers (portable sm_80+ features: mma.sync / ldmatrix / cp.async)
// ---------------------------------------------------------------------------
__device__ __forceinline__ uint32_t smem_to_u32(const void* p) {
    uint32_t a;
    asm("{ .reg .u64 t; cvta.to.shared.u64 t, %1; cvt.u32.u64 %0, t; }"
        : "=r"(a) : "l"(p));
    return a;
}

__device__ __forceinline__ void cp_async16(uint32_t dst, const void* src) {
    asm volatile("cp.async.cg.shared.global [%0], [%1], 16;"
                 :: "r"(dst), "l"(src));
}
#define CP_COMMIT() asm volatile("cp.async.commit_group;" ::: "memory")
#define CP_WAIT1()  asm volatile("cp.async.wait_group 1;" ::: "memory")
#define CP_WAIT0()  asm volatile("cp.async.wait_group 0;" ::: "memory")

__device__ __forceinline__ void ldsm_x4(uint32_t& r0, uint32_t& r1,
                                        uint32_t& r2, uint32_t& r3, uint32_t addr) {
    asm volatile("ldmatrix.sync.aligned.m8n8.x4.shared.b16 {%0,%1,%2,%3}, [%4];"
                 : "=r"(r0), "=r"(r1), "=r"(r2), "=r"(r3) : "r"(addr));
}

__device__ __forceinline__ void ldsm_x4t(uint32_t& r0, uint32_t& r1,
                                         uint32_t& r2, uint32_t& r3, uint32_t addr) {
    asm volatile("ldmatrix.sync.aligned.m8n8.x4.trans.shared.b16 {%0,%1,%2,%3}, [%4];"
                 : "=r"(r0), "=r"(r1), "=r"(r2), "=r"(r3) : "r"(addr));
}

__device__ __forceinline__ void mma16816(float* c, const uint32_t* a, const uint32_t* b) {
    asm volatile(
        "mma.sync.aligned.m16n8k16.row.col.f32.bf16.bf16.f32 "
        "{%0,%1,%2,%3}, {%4,%5,%6,%7}, {%8,%9}, {%0,%1,%2,%3};"
        : "+f"(c[0]), "+f"(c[1]), "+f"(c[2]), "+f"(c[3])
        : "r"(a[0]), "r"(a[1]), "r"(a[2]), "r"(a[3]), "r"(b[0]), "r"(b[1]));
}

// ---------------------------------------------------------------------------
// hi/lo bf16 split of X [M x 1024]
// ---------------------------------------------------------------------------
__global__ void __launch_bounds__(256) xsplit_kernel(
    const float* __restrict__ X,
    __nv_bfloat16* __restrict__ Xh, __nv_bfloat16* __restrict__ Xl)
{
    int i = (blockIdx.x * 256 + threadIdx.x) * 4;
    float4 v = *(const float4*)(X + i);
    __nv_bfloat162 hp0 = __floats2bfloat162_rn(v.x, v.y);
    __nv_bfloat162 hp1 = __floats2bfloat162_rn(v.z, v.w);
    __nv_bfloat162 lp0 = __floats2bfloat162_rn(v.x - __bfloat162float(hp0.x),
                                               v.y - __bfloat162float(hp0.y));
    __nv_bfloat162 lp1 = __floats2bfloat162_rn(v.z - __bfloat162float(hp1.x),
                                               v.w - __bfloat162float(hp1.y));
    *(__nv_bfloat162*)(Xh + i)     = hp0;
    *(__nv_bfloat162*)(Xh + i + 2) = hp1;
    *(__nv_bfloat162*)(Xl + i)     = lp0;
    *(__nv_bfloat162*)(Xl + i + 2) = lp1;
}

// ---------------------------------------------------------------------------
// Transpose + split all 4 weights in one launch (z = which weight)
// ---------------------------------------------------------------------------
__global__ void __launch_bounds__(256) wsplit4_kernel(
    const float* __restrict__ W0, const float* __restrict__ W1,
    const float* __restrict__ W2, const float* __restrict__ W3)
{
    __shared__ float t[32][33];
    const int z = blockIdx.z;
    const float* W = (z == 0) ? W0 : (z == 1) ? W1 : (z == 2) ? W2 : W3;
    __nv_bfloat16* Wht = g_Wht + (size_t)z * DD * DD;
    __nv_bfloat16* Wlt = g_Wlt + (size_t)z * DD * DD;

    int tx = threadIdx.x, ty = threadIdx.y;   // (32, 8)
    int n0 = blockIdx.x * 32, k0 = blockIdx.y * 32;
#pragma unroll
    for (int i = 0; i < 4; i++)
        t[ty + i * 8][tx] = W[(size_t)(k0 + ty + i * 8) * DD + n0 + tx];
    __syncthreads();
#pragma unroll
    for (int i = 0; i < 4; i++) {
        float v = t[tx][ty + i * 8];
        __nv_bfloat16 h = __float2bfloat16_rn(v);
        __nv_bfloat16 l = __float2bfloat16_rn(v - __bfloat162float(h));
        size_t idx = (size_t)(n0 + ty + i * 8) * DD + k0 + tx;
        Wht[idx] = h;
        Wlt[idx] = l;
    }
}

// ---------------------------------------------------------------------------
// Shared GEMM mainloop: acc = (Ah+Al)[128 rows, 1024] @ (Bh+Bl)[128 rows, 1024]^T
//   3-term split (hh + hl + lh). cp.async double-buffered, ONE barrier/chunk.
// ---------------------------------------------------------------------------
#define KC 64
#define ASTRIDE 72
#define TILE_B (128 * ASTRIDE * 2)
#define BUF_B  (4 * TILE_B)
#define GEMM_SMEM (2 * BUF_B)

__device__ __forceinline__ void gemm_mainloop(
    uint32_t smem_u, int tid, int lane, int wm, int wn,
    const __nv_bfloat16* s0, const __nv_bfloat16* s1,
    const __nv_bfloat16* s2, const __nv_bfloat16* s3,
    float acc[2][8][4])
{
    const __nv_bfloat16* srcs[4] = { s0, s1, s2, s3 };

    auto issue_chunk = [&](int c) {
        const uint32_t boff = smem_u + (uint32_t)(c & 1) * BUF_B;
#pragma unroll
        for (int i = 0; i < 16; i++) {
            int seg = tid + i * 256;
            int t = seg >> 10;
            int rem = seg & 1023;
            int row = rem >> 3, g = rem & 7;
            uint32_t dst = boff + (uint32_t)t * TILE_B
                         + (uint32_t)(row * ASTRIDE + g * 8) * 2;
            cp_async16(dst, srcs[t] + (size_t)row * DD + c * KC + g * 8);
        }
    };

    const int a_row = wm * 32 + (lane & 15);
    const int a_kof = (lane >> 4) * 8;
    const int b_row = wn * 64 + (lane & 7) + (lane >> 4) * 8;
    const int b_kof = ((lane >> 3) & 1) * 8;

    issue_chunk(0);
    CP_COMMIT();

    for (int c = 0; c < 16; c++) {
        CP_WAIT0();
        __syncthreads();                    // chunk c visible; prev reads done
        if (c < 15) { issue_chunk(c + 1); CP_COMMIT(); }

        const uint32_t boff = smem_u + (uint32_t)(c & 1) * BUF_B;
        const uint32_t tAh = boff;
        const uint32_t tAl = boff + TILE_B;
        const uint32_t tBh = boff + 2 * TILE_B;
        const uint32_t tBl = boff + 3 * TILE_B;

#pragma unroll
        for (int kb = 0; kb < KC; kb += 16) {
            uint32_t ah[2][4], al[2][4], bh[8][2], bl[8][2];
#pragma unroll
            for (int mi = 0; mi < 2; mi++) {
                uint32_t ao = (uint32_t)((a_row + mi * 16) * ASTRIDE + kb + a_kof) * 2;
                ldsm_x4(ah[mi][0], ah[mi][1], ah[mi][2], ah[mi][3], tAh + ao);
                ldsm_x4(al[mi][0], al[mi][1], al[mi][2], al[mi][3], tAl + ao);
            }
#pragma unroll
            for (int p = 0; p < 4; p++) {
                uint32_t bo = (uint32_t)((b_row + p * 16) * ASTRIDE + kb + b_kof) * 2;
                ldsm_x4(bh[2 * p][0], bh[2 * p][1], bh[2 * p + 1][0], bh[2 * p + 1][1], tBh + bo);
                ldsm_x4(bl[2 * p][0], bl[2 * p][1], bl[2 * p + 1][0], bl[2 * p + 1][1], tBl + bo);
            }
#pragma unroll
            for (int mi = 0; mi < 2; mi++)
#pragma unroll
                for (int ni = 0; ni < 8; ni++) {
                    mma16816(acc[mi][ni], ah[mi], bh[ni]);
                    mma16816(acc[mi][ni], ah[mi], bl[ni]);
                    mma16816(acc[mi][ni], al[mi], bh[ni]);
                }
        }
        __syncthreads();                    // reads of chunk c done before overwrite
    }
}

// ---------------------------------------------------------------------------
// Fused QKV projection GEMM. grid (8, 64, 3); z selects Wq/Wk/Wv + output.
// Epilogue: (acc + bias) * scale -> bf16 hi/lo, heads layout [B,H,S,HD].
// ---------------------------------------------------------------------------
__global__ void __launch_bounds__(256, 1) gemm_qkv_kernel(
    const float* __restrict__ bq, const float* __restrict__ bk,
    const float* __restrict__ bv)
{
    extern __shared__ char smem[];
    const uint32_t smem_u = smem_to_u32(smem);

    const int tid = threadIdx.x, wid = tid >> 5, lane = tid & 31;
    const int mtile = blockIdx.y, ntile = blockIdx.x, z = blockIdx.z;
    const int wm = wid & 3, wn = wid >> 2;

    const __nv_bfloat16* Bh_g = g_Wht + (size_t)z * DD * DD;
    const __nv_bfloat16* Bl_g = g_Wlt + (size_t)z * DD * DD;
    const float* bias = (z == 0) ? bq : (z == 1) ? bk : bv;
    __nv_bfloat16* Ch = (z == 0) ? g_Qh : (z == 1) ? g_Kh : g_Vh;
    __nv_bfloat16* Cl = (z == 0) ? g_Ql : (z == 1) ? g_Kl : g_Vl;
    const float scale = (z == 0) ? 0.125f : 1.0f;

    float acc[2][8][4];
#pragma unroll
    for (int mi = 0; mi < 2; mi++)
#pragma unroll
        for (int ni = 0; ni < 8; ni++)
#pragma unroll
            for (int r = 0; r < 4; r++) acc[mi][ni][r] = 0.0f;

    gemm_mainloop(smem_u, tid, lane, wm, wn,
                  g_Xh + (size_t)mtile * 128 * DD,
                  g_Xl + (size_t)mtile * 128 * DD,
                  Bh_g + (size_t)ntile * 128 * DD,
                  Bl_g + (size_t)ntile * 128 * DD, acc);

    const int mb = mtile * 128 + wm * 32 + (lane >> 2);
    const int nb0 = ntile * 128 + wn * 64 + (lane & 3) * 2;

#pragma unroll
    for (int mi = 0; mi < 2; mi++)
#pragma unroll
        for (int ni = 0; ni < 8; ni++) {
            int n = nb0 + ni * 8;
            float2 bsv = *(const float2*)(bias + n);
            int hh2 = n >> 6, hd = n & 63;
#pragma unroll
            for (int half = 0; half < 2; half++) {
                int mg = mb + mi * 16 + half * 8;
                float v0 = (acc[mi][ni][half * 2 + 0] + bsv.x) * scale;
                float v1 = (acc[mi][ni][half * 2 + 1] + bsv.y) * scale;
                __nv_bfloat162 hp = __floats2bfloat162_rn(v0, v1);
                __nv_bfloat162 lp = __floats2bfloat162_rn(
                    v0 - __bfloat162float(hp.x), v1 - __bfloat162float(hp.y));
                int bq2 = mg >> 12, sseq = mg & 4095;
                size_t off = ((size_t)(bq2 * HH + hh2) * SS + sseq) * HD + hd;
                *(__nv_bfloat162*)(Ch + off) = hp;
                *(__nv_bfloat162*)(Cl + off) = lp;
            }
        }
}

// ---------------------------------------------------------------------------
// Output projection GEMM: out = (Ah+Al) @ Wo^T + bo, fp32 row-major.
// ---------------------------------------------------------------------------
__global__ void __launch_bounds__(256, 1) gemm_out_kernel(
    const float* __restrict__ bo, float* __restrict__ Cf)
{
    extern __shared__ char smem[];
    const uint32_t smem_u = smem_to_u32(smem);

    const int tid = threadIdx.x, wid = tid >> 5, lane = tid & 31;
    const int mtile = blockIdx.y, ntile = blockIdx.x;
    const int wm = wid & 3, wn = wid >> 2;

    float acc[2][8][4];
#pragma unroll
    for (int mi = 0; mi < 2; mi++)
#pragma unroll
        for (int ni = 0; ni < 8; ni++)
#pragma unroll
            for (int r = 0; r < 4; r++) acc[mi][ni][r] = 0.0f;

    gemm_mainloop(smem_u, tid, lane, wm, wn,
                  g_Ah + (size_t)mtile * 128 * DD,
                  g_Al + (size_t)mtile * 128 * DD,
                  g_Wht + 3 * (size_t)DD * DD + (size_t)ntile * 128 * DD,
                  g_Wlt + 3 * (size_t)DD * DD + (size_t)ntile * 128 * DD, acc);

    const int mb = mtile * 128 + wm * 32 + (lane >> 2);
    const int nb0 = ntile * 128 + wn * 64 + (lane & 3) * 2;

#pragma unroll
    for (int mi = 0; mi < 2; mi++)
#pragma unroll
        for (int ni = 0; ni < 8; ni++) {
            int n = nb0 + ni * 8;
            float2 bsv = *(const float2*)(bo + n);
#pragma unroll
            for (int half = 0; half < 2; half++) {
                int m = mb + mi * 16 + half * 8;
                float2 o;
                o.x = acc[mi][ni][half * 2 + 0] + bsv.x;
                o.y = acc[mi][ni][half * 2 + 1] + bsv.y;
                *(float2*)(Cf + (size_t)m * DD + n) = o;
            }
        }
}

// ---------------------------------------------------------------------------
// Flash attention with mma.sync bf16 hi/lo splits (one barrier per KV tile).
// ---------------------------------------------------------------------------
#define TQ 128
#define TK 64
#define QST 72
#define QTILE_B (128 * QST * 2)   // 18432
#define KTILE_B (64 * QST * 2)    // 9216
#define ATTN_SMEM (2 * QTILE_B + 2 * 4 * KTILE_B)  // 110592

__global__ void __launch_bounds__(256, 1) attn_mma_kernel()
{
    extern __shared__ char smem[];
    const uint32_t smem_u = smem_to_u32(smem);
    const uint32_t sQh = smem_u;
    const uint32_t sQl = smem_u + QTILE_B;
    const uint32_t sBuf = smem_u + 2 * QTILE_B;

    const int tid = threadIdx.x, wid = tid >> 5, lane = tid & 31;
    const int b = blockIdx.z, h = blockIdx.y;
    const int q0 = blockIdx.x * TQ;
    const size_t bhoff = (size_t)(b * HH + h) * SS * HD;

    // Stage Q (hi + lo)
    {
        const __nv_bfloat16* qsrc[2] = { g_Qh + bhoff + (size_t)q0 * HD,
                                         g_Ql + bhoff + (size_t)q0 * HD };
#pragma unroll
        for (int i = 0; i < 8; i++) {
            int seg = tid + i * 256;
            int arr = seg >> 10, rem = seg & 1023;
            int row = rem >> 3, g = rem & 7;
            cp_async16(smem_u + (uint32_t)arr * QTILE_B + (uint32_t)(row * QST + g * 8) * 2,
                       qsrc[arr] + (size_t)row * HD + g * 8);
        }
    }
    CP_COMMIT();

    const __nv_bfloat16* kvsrc[4] = { g_Kh + bhoff, g_Kl + bhoff,
                                      g_Vh + bhoff, g_Vl + bhoff };
    auto issue_kv = [&](int t) {
        const uint32_t boff = sBuf + (uint32_t)(t & 1) * (4 * KTILE_B);
#pragma unroll
        for (int i = 0; i < 8; i++) {
            int seg = tid + i * 256;
            int arr = seg >> 9;
            int rem = seg & 511;
            int row = rem >> 3, g = rem & 7;
            cp_async16(boff + (uint32_t)arr * KTILE_B + (uint32_t)(row * QST + g * 8) * 2,
                       kvsrc[arr] + (size_t)(t * TK + row) * HD + g * 8);
        }
    };
    issue_kv(0); CP_COMMIT();

    CP_WAIT1();        // Q staged
    __syncthreads();

    uint32_t qh[4][4], ql[4][4];
    {
        const int a_row = wid * 16 + (lane & 15);
        const int a_kof = (lane >> 4) * 8;
#pragma unroll
        for (int k = 0; k < 4; k++) {
            uint32_t ao = (uint32_t)(a_row * QST + k * 16 + a_kof) * 2;
            ldsm_x4(qh[k][0], qh[k][1], qh[k][2], qh[k][3], sQh + ao);
            ldsm_x4(ql[k][0], ql[k][1], ql[k][2], ql[k][3], sQl + ao);
        }
    }

    float m0 = -1e30f, m1 = -1e30f, l0 = 0.0f, l1 = 0.0f;
    float o[8][4];
#pragma unroll
    for (int nb = 0; nb < 8; nb++)
#pragma unroll
        for (int r = 0; r < 4; r++) o[nb][r] = 0.0f;

    const int b_row = (lane & 7) + (lane >> 4) * 8;
    const int b_kof = ((lane >> 3) & 1) * 8;
    const int v_row = (lane & 15);
    const int v_col = (lane >> 4) * 8;

    for (int t = 0; t < SS / TK; t++) {
        CP_WAIT0();
        __syncthreads();                 // tile t visible; prev tile reads done
        if (t < SS / TK - 1) { issue_kv(t + 1); CP_COMMIT(); }

        const uint32_t boff = sBuf + (uint32_t)(t & 1) * (4 * KTILE_B);
        const uint32_t tKh = boff, tKl = boff + KTILE_B;
        const uint32_t tVh = boff + 2 * KTILE_B, tVl = boff + 3 * KTILE_B;

        // ---- S = Q K^T (3-term split) ----
        float s[8][4];
#pragma unroll
        for (int nb = 0; nb < 8; nb++)
#pragma unroll
            for (int r = 0; r < 4; r++) s[nb][r] = 0.0f;

#pragma unroll
        for (int k = 0; k < 4; k++) {
            uint32_t kh[8][2], kl[8][2];
#pragma unroll
            for (int p = 0; p < 4; p++) {
                uint32_t bo = (uint32_t)((p * 16 + b_row) * QST + k * 16 + b_kof) * 2;
                ldsm_x4(kh[2 * p][0], kh[2 * p][1], kh[2 * p + 1][0], kh[2 * p + 1][1], tKh + bo);
                ldsm_x4(kl[2 * p][0], kl[2 * p][1], kl[2 * p + 1][0], kl[2 * p + 1][1], tKl + bo);
            }
#pragma unroll
            for (int nb = 0; nb < 8; nb++) {
                mma16816(s[nb], qh[k], kh[nb]);
                mma16816(s[nb], qh[k], kl[nb]);
                mma16816(s[nb], ql[k], kh[nb]);
            }
        }

        // ---- online softmax ----
        float rm0 = -1e30f, rm1 = -1e30f;
#pragma unroll
        for (int nb = 0; nb < 8; nb++) {
            rm0 = fmaxf(rm0, fmaxf(s[nb][0], s[nb][1]));
            rm1 = fmaxf(rm1, fmaxf(s[nb][2], s[nb][3]));
        }
        rm0 = fmaxf(rm0, __shfl_xor_sync(0xffffffffu, rm0, 1));
        rm0 = fmaxf(rm0, __shfl_xor_sync(0xffffffffu, rm0, 2));
        rm1 = fmaxf(rm1, __shfl_xor_sync(0xffffffffu, rm1, 1));
        rm1 = fmaxf(rm1, __shfl_xor_sync(0xffffffffu, rm1, 2));

        float mn0 = fmaxf(m0, rm0), mn1 = fmaxf(m1, rm1);
        float al0 = __expf(m0 - mn0), al1 = __expf(m1 - mn1);
        m0 = mn0; m1 = mn1;

        float rs0 = 0.0f, rs1 = 0.0f;
#pragma unroll
        for (int nb = 0; nb < 8; nb++) {
            s[nb][0] = __expf(s[nb][0] - mn0);
            s[nb][1] = __expf(s[nb][1] - mn0);
            s[nb][2] = __expf(s[nb][2] - mn1);
            s[nb][3] = __expf(s[nb][3] - mn1);
            rs0 += s[nb][0] + s[nb][1];
            rs1 += s[nb][2] + s[nb][3];
        }
        rs0 += __shfl_xor_sync(0xffffffffu, rs0, 1);
        rs0 += __shfl_xor_sync(0xffffffffu, rs0, 2);
        rs1 += __shfl_xor_sync(0xffffffffu, rs1, 1);
        rs1 += __shfl_xor_sync(0xffffffffu, rs1, 2);
        l0 = l0 * al0 + rs0;
        l1 = l1 * al1 + rs1;
#pragma unroll
        for (int nb = 0; nb < 8; nb++) {
            o[nb][0] *= al0; o[nb][1] *= al0;
            o[nb][2] *= al1; o[nb][3] *= al1;
        }

        // ---- pack P into A-operand fragments (hi + lo) ----
        uint32_t ph[4][4], pl[4][4];
#pragma unroll
        for (int j = 0; j < 4; j++) {
            float pv[4][2] = {
                { s[2 * j][0],     s[2 * j][1]     },
                { s[2 * j][2],     s[2 * j][3]     },
                { s[2 * j + 1][0], s[2 * j + 1][1] },
                { s[2 * j + 1][2], s[2 * j + 1][3] } };
#pragma unroll
            for (int r = 0; r < 4; r++) {
                __nv_bfloat162 hp = __floats2bfloat162_rn(pv[r][0], pv[r][1]);
                __nv_bfloat162 lp = __floats2bfloat162_rn(
                    pv[r][0] - __bfloat162float(hp.x),
                    pv[r][1] - __bfloat162float(hp.y));
                ph[j][r] = *reinterpret_cast<uint32_t*>(&hp);
                pl[j][r] = *reinterpret_cast<uint32_t*>(&lp);
            }
        }

        // ---- O += P V (3-term split) ----
#pragma unroll
        for (int j = 0; j < 4; j++) {
            uint32_t vh[8][2], vl[8][2];
#pragma unroll
            for (int p = 0; p < 4; p++) {
                uint32_t vo = (uint32_t)((j * 16 + v_row) * QST + p * 16 + v_col) * 2;
                ldsm_x4t(vh[2 * p][0], vh[2 * p][1], vh[2 * p + 1][0], vh[2 * p + 1][1], tVh + vo);
                ldsm_x4t(vl[2 * p][0], vl[2 * p][1], vl[2 * p + 1][0], vl[2 * p + 1][1], tVl + vo);
            }
#pragma unroll
            for (int nb = 0; nb < 8; nb++) {
                mma16816(o[nb], ph[j], vh[nb]);
                mma16816(o[nb], ph[j], vl[nb]);
                mma16816(o[nb], pl[j], vh[nb]);
            }
        }
    }

    // ---- epilogue: normalize, split hi/lo, write row-major [M, D] ----
    const float inv0 = 1.0f / l0, inv1 = 1.0f / l1;
    const int qrow = q0 + wid * 16 + (lane >> 2);
    const size_t mrow0 = (size_t)(b * SS + qrow);
    const size_t mrow1 = mrow0 + 8;
    const int colb = h * HD + (lane & 3) * 2;
#pragma unroll
    for (int nb = 0; nb < 8; nb++) {
        int col = colb + nb * 8;
        float x0 = o[nb][0] * inv0, x1 = o[nb][1] * inv0;
        float x2 = o[nb][2] * inv1, x3 = o[nb][3] * inv1;
        __nv_bfloat162 h0 = __floats2bfloat162_rn(x0, x1);
        __nv_bfloat162 g0 = __floats2bfloat162_rn(
            x0 - __bfloat162float(h0.x), x1 - __bfloat162float(h0.y));
        __nv_bfloat162 h1 = __floats2bfloat162_rn(x2, x3);
        __nv_bfloat162 g1 = __floats2bfloat162_rn(
            x2 - __bfloat162float(h1.x), x3 - __bfloat162float(h1.y));
        *(__nv_bfloat162*)(g_Ah + mrow0 * DD + col) = h0;
        *(__nv_bfloat162*)(g_Al + mrow0 * DD + col) = g0;
        *(__nv_bfloat162*)(g_Ah + mrow1 * DD + col) = h1;
        *(__nv_bfloat162*)(g_Al + mrow1 * DD + col) = g1;
    }
}

// ---------------------------------------------------------------------------
// Launch
// ---------------------------------------------------------------------------
extern "C" void kernel_launch(void* const* d_in, const int* in_sizes, int n_in,
                              void* d_out, int out_size)
{
    (void)in_sizes; (void)n_in; (void)out_size;
    const float* X  = (const float*)d_in[0];
    const float* Wq = (const float*)d_in[1];
    const float* bq = (const float*)d_in[2];
    const float* Wk = (const float*)d_in[3];
    const float* bk = (const float*)d_in[4];
    const float* Wv = (const float*)d_in[5];
    const float* bv = (const float*)d_in[6];
    const float* Wo = (const float*)d_in[7];
    const float* bo = (const float*)d_in[8];
    float* out = (float*)d_out;

    __nv_bfloat16* pXh;
    __nv_bfloat16* pXl;
    cudaGetSymbolAddress((void**)&pXh, g_Xh);
    cudaGetSymbolAddress((void**)&pXl, g_Xl);

    cudaFuncSetAttribute(gemm_qkv_kernel,
                         cudaFuncAttributeMaxDynamicSharedMemorySize, GEMM_SMEM);
    cudaFuncSetAttribute(gemm_out_kernel,
                         cudaFuncAttributeMaxDynamicSharedMemorySize, GEMM_SMEM);
    cudaFuncSetAttribute(attn_mma_kernel,
                         cudaFuncAttributeMaxDynamicSharedMemorySize, ATTN_SMEM);

    // Prep: split X, split+transpose all 4 weights
    xsplit_kernel<<<MM * DD / 4 / 256, 256>>>(X, pXh, pXl);
    dim3 gW(32, 32, 4), bW(32, 8);
    wsplit4_kernel<<<gW, bW>>>(Wq, Wk, Wv, Wo);

    // Fused Q/K/V projections
    dim3 gQKV(DD / 128, MM / 128, 3);   // (8, 64, 3)
    gemm_qkv_kernel<<<gQKV, 256, GEMM_SMEM>>>(bq, bk, bv);

    // Attention
    dim3 gattn(SS / TQ, HH, BB);        // (32, 16, 2)
    attn_mma_kernel<<<gattn, 256, ATTN_SMEM>>>();

    // Output projection
    dim3 gO(DD / 128, MM / 128);        // (8, 64)
    gemm_out_kernel<<<gO, 256, GEMM_SMEM>>>(bo, out);
}

// round 6
// speedup vs baseline: 3.1495x; 1.0272x over previous
#include <cuda_runtime.h>
#include <cuda_bf16.h>
#include <cstdint>
#include <math.h>

// Problem constants
#define BB 2
#define SS 4096
#define DD 1024
#define HH 16
#define HD 64
#define MM (BB * SS)   // 8192

// ---------------------------------------------------------------------------
// Scratch (device globals)
// ---------------------------------------------------------------------------
__device__ __nv_bfloat16 g_Xh[MM * DD];
__device__ __nv_bfloat16 g_Xl[MM * DD];
__device__ __nv_bfloat16 g_Wht[4 * DD * DD];
__device__ __nv_bfloat16 g_Wlt[4 * DD * DD];
__device__ __nv_bfloat16 g_Qh[MM * DD];
__device__ __nv_bfloat16 g_Ql[MM * DD];
__device__ __nv_bfloat16 g_Kh[MM * DD];
__device__ __nv_bfloat16 g_Kl[MM * DD];
__device__ __nv_bfloat16 g_Vh[MM * DD];
__device__ __nv_bfloat16 g_Vl[MM * DD];
__device__ __nv_bfloat16 g_Ah[MM * DD];
__device__ __nv_bfloat16 g_Al[MM * DD];

// ---------------------------------------------------------------------------
// PTX helpers
// ---------------------------------------------------------------------------
__device__ __forceinline__ uint32_t smem_to_u32(const void* p) {
    uint32_t a;
    asm("{ .reg .u64 t; cvta.to.shared.u64 t, %1; cvt.u32.u64 %0, t; }"
        : "=r"(a) : "l"(p));
    return a;
}

__device__ __forceinline__ void cp_async16(uint32_t dst, const void* src) {
    asm volatile("cp.async.cg.shared.global [%0], [%1], 16;"
                 :: "r"(dst), "l"(src));
}
#define CP_COMMIT() asm volatile("cp.async.commit_group;" ::: "memory")
#define CP_WAIT1()  asm volatile("cp.async.wait_group 1;" ::: "memory")
#define CP_WAIT0()  asm volatile("cp.async.wait_group 0;" ::: "memory")

__device__ __forceinline__ void ldsm_x4(uint32_t& r0, uint32_t& r1,
                                        uint32_t& r2, uint32_t& r3, uint32_t addr) {
    asm volatile("ldmatrix.sync.aligned.m8n8.x4.shared.b16 {%0,%1,%2,%3}, [%4];"
                 : "=r"(r0), "=r"(r1), "=r"(r2), "=r"(r3) : "r"(addr));
}

__device__ __forceinline__ void ldsm_x4t(uint32_t& r0, uint32_t& r1,
                                         uint32_t& r2, uint32_t& r3, uint32_t addr) {
    asm volatile("ldmatrix.sync.aligned.m8n8.x4.trans.shared.b16 {%0,%1,%2,%3}, [%4];"
                 : "=r"(r0), "=r"(r1), "=r"(r2), "=r"(r3) : "r"(addr));
}

__device__ __forceinline__ void mma16816(float* c, const uint32_t* a, const uint32_t* b) {
    asm volatile(
        "mma.sync.aligned.m16n8k16.row.col.f32.bf16.bf16.f32 "
        "{%0,%1,%2,%3}, {%4,%5,%6,%7}, {%8,%9}, {%0,%1,%2,%3};"
        : "+f"(c[0]), "+f"(c[1]), "+f"(c[2]), "+f"(c[3])
        : "r"(a[0]), "r"(a[1]), "r"(a[2]), "r"(a[3]), "r"(b[0]), "r"(b[1]));
}

// ---------------------------------------------------------------------------
// hi/lo bf16 split of X
// ---------------------------------------------------------------------------
__global__ void __launch_bounds__(256) xsplit_kernel(
    const float* __restrict__ X,
    __nv_bfloat16* __restrict__ Xh, __nv_bfloat16* __restrict__ Xl)
{
    int i = (blockIdx.x * 256 + threadIdx.x) * 4;
    float4 v = *(const float4*)(X + i);
    __nv_bfloat162 hp0 = __floats2bfloat162_rn(v.x, v.y);
    __nv_bfloat162 hp1 = __floats2bfloat162_rn(v.z, v.w);
    __nv_bfloat162 lp0 = __floats2bfloat162_rn(v.x - __bfloat162float(hp0.x),
                                               v.y - __bfloat162float(hp0.y));
    __nv_bfloat162 lp1 = __floats2bfloat162_rn(v.z - __bfloat162float(hp1.x),
                                               v.w - __bfloat162float(hp1.y));
    *(__nv_bfloat162*)(Xh + i)     = hp0;
    *(__nv_bfloat162*)(Xh + i + 2) = hp1;
    *(__nv_bfloat162*)(Xl + i)     = lp0;
    *(__nv_bfloat162*)(Xl + i + 2) = lp1;
}

// ---------------------------------------------------------------------------
// Transpose + split all 4 weights
// ---------------------------------------------------------------------------
__global__ void __launch_bounds__(256) wsplit4_kernel(
    const float* __restrict__ W0, const float* __restrict__ W1,
    const float* __restrict__ W2, const float* __restrict__ W3)
{
    __shared__ float t[32][33];
    const int z = blockIdx.z;
    const float* W = (z == 0) ? W0 : (z == 1) ? W1 : (z == 2) ? W2 : W3;
    __nv_bfloat16* Wht = g_Wht + (size_t)z * DD * DD;
    __nv_bfloat16* Wlt = g_Wlt + (size_t)z * DD * DD;

    int tx = threadIdx.x, ty = threadIdx.y;
    int n0 = blockIdx.x * 32, k0 = blockIdx.y * 32;
#pragma unroll
    for (int i = 0; i < 4; i++)
        t[ty + i * 8][tx] = W[(size_t)(k0 + ty + i * 8) * DD + n0 + tx];
    __syncthreads();
#pragma unroll
    for (int i = 0; i < 4; i++) {
        float v = t[tx][ty + i * 8];
        __nv_bfloat16 h = __float2bfloat16_rn(v);
        __nv_bfloat16 l = __float2bfloat16_rn(v - __bfloat162float(h));
        size_t idx = (size_t)(n0 + ty + i * 8) * DD + k0 + tx;
        Wht[idx] = h;
        Wlt[idx] = l;
    }
}

// ---------------------------------------------------------------------------
// GEMM mainloop (64x128 CTA tile, 128 threads, KC=32, double-buffered)
//   acc = (Ah+Al)[64, 1024] @ (Bh+Bl)[128, 1024]^T  (3-term split)
//   4 warps: wm in {0,1} (32 rows), wn in {0,1} (64 cols)
// ---------------------------------------------------------------------------
#define KC 32
#define GSTRIDE 40                              // padded row elems (80B = 5x16B)
#define TILE_A (64 * GSTRIDE * 2)               // 5120 B
#define TILE_BB (128 * GSTRIDE * 2)             // 10240 B
#define BUF_B  (2 * TILE_A + 2 * TILE_BB)       // 30720 B
#define GEMM_SMEM (2 * BUF_B)                   // 61440 B

__device__ __forceinline__ void gemm_mainloop(
    uint32_t smem_u, int tid, int lane, int wm, int wn,
    const __nv_bfloat16* ah_g, const __nv_bfloat16* al_g,
    const __nv_bfloat16* bh_g, const __nv_bfloat16* bl_g,
    float acc[2][8][4])
{
    auto issue_chunk = [&](int c) {
        const uint32_t boff = smem_u + (uint32_t)(c & 1) * BUF_B;
        // A tiles: 2 x 64 rows x 4 groups = 512 segs
#pragma unroll
        for (int i = 0; i < 4; i++) {
            int seg = tid + i * 128;          // 0..511
            int t = seg >> 8;                 // 0,1
            int rem = seg & 255;
            int row = rem >> 2, g = rem & 3;
            const __nv_bfloat16* src = t ? al_g : ah_g;
            cp_async16(boff + (uint32_t)t * TILE_A
                       + (uint32_t)(row * GSTRIDE + g * 8) * 2,
                       src + (size_t)row * DD + c * KC + g * 8);
        }
        // B tiles: 2 x 128 rows x 4 groups = 1024 segs
#pragma unroll
        for (int i = 0; i < 8; i++) {
            int seg = tid + i * 128;          // 0..1023
            int t = seg >> 9;                 // 0,1
            int rem = seg & 511;
            int row = rem >> 2, g = rem & 3;
            const __nv_bfloat16* src = t ? bl_g : bh_g;
            cp_async16(boff + 2 * TILE_A + (uint32_t)t * TILE_BB
                       + (uint32_t)(row * GSTRIDE + g * 8) * 2,
                       src + (size_t)row * DD + c * KC + g * 8);
        }
    };

    const int a_row = wm * 32 + (lane & 15);
    const int a_kof = (lane >> 4) * 8;
    const int b_row = wn * 64 + (lane & 7) + (lane >> 4) * 8;
    const int b_kof = ((lane >> 3) & 1) * 8;

    issue_chunk(0);
    CP_COMMIT();

    for (int c = 0; c < 32; c++) {
        CP_WAIT0();
        __syncthreads();
        if (c < 31) { issue_chunk(c + 1); CP_COMMIT(); }

        const uint32_t boff = smem_u + (uint32_t)(c & 1) * BUF_B;
        const uint32_t tAh = boff;
        const uint32_t tAl = boff + TILE_A;
        const uint32_t tBh = boff + 2 * TILE_A;
        const uint32_t tBl = boff + 2 * TILE_A + TILE_BB;

#pragma unroll
        for (int kb = 0; kb < KC; kb += 16) {
            uint32_t ah[2][4], al[2][4], bh[8][2], bl[8][2];
#pragma unroll
            for (int mi = 0; mi < 2; mi++) {
                uint32_t ao = (uint32_t)((a_row - wm * 32 + mi * 16 + wm * 32) * GSTRIDE + kb + a_kof) * 2;
                ldsm_x4(ah[mi][0], ah[mi][1], ah[mi][2], ah[mi][3],
                        tAh + (uint32_t)((a_row + mi * 16) * GSTRIDE + kb + a_kof) * 2);
                ldsm_x4(al[mi][0], al[mi][1], al[mi][2], al[mi][3],
                        tAl + (uint32_t)((a_row + mi * 16) * GSTRIDE + kb + a_kof) * 2);
                (void)ao;
            }
#pragma unroll
            for (int p = 0; p < 4; p++) {
                uint32_t bo = (uint32_t)((p * 16 + b_row) * GSTRIDE + kb + b_kof) * 2;
                ldsm_x4(bh[2 * p][0], bh[2 * p][1], bh[2 * p + 1][0], bh[2 * p + 1][1], tBh + bo);
                ldsm_x4(bl[2 * p][0], bl[2 * p][1], bl[2 * p + 1][0], bl[2 * p + 1][1], tBl + bo);
            }
#pragma unroll
            for (int mi = 0; mi < 2; mi++)
#pragma unroll
                for (int ni = 0; ni < 8; ni++) {
                    mma16816(acc[mi][ni], ah[mi], bh[ni]);
                    mma16816(acc[mi][ni], ah[mi], bl[ni]);
                    mma16816(acc[mi][ni], al[mi], bh[ni]);
                }
        }
        __syncthreads();
    }
}

// A-row slice note: warp covers rows [wm*32, wm*32+32); ldsm rows a_row + mi*16
// with a_row = wm*32 + (lane&15) stays within the 64-row A tile for wm in {0,1}.

// ---------------------------------------------------------------------------
// Fused QKV projection GEMM. grid (8, 128, 3)
// ---------------------------------------------------------------------------
__global__ void __launch_bounds__(128, 3) gemm_qkv_kernel(
    const float* __restrict__ bq, const float* __restrict__ bk,
    const float* __restrict__ bv)
{
    extern __shared__ char smem[];
    const uint32_t smem_u = smem_to_u32(smem);

    const int tid = threadIdx.x, wid = tid >> 5, lane = tid & 31;
    const int mtile = blockIdx.y, ntile = blockIdx.x, z = blockIdx.z;
    const int wm = wid & 1, wn = wid >> 1;

    const __nv_bfloat16* Bh_g = g_Wht + (size_t)z * DD * DD;
    const __nv_bfloat16* Bl_g = g_Wlt + (size_t)z * DD * DD;
    const float* bias = (z == 0) ? bq : (z == 1) ? bk : bv;
    __nv_bfloat16* Ch = (z == 0) ? g_Qh : (z == 1) ? g_Kh : g_Vh;
    __nv_bfloat16* Cl = (z == 0) ? g_Ql : (z == 1) ? g_Kl : g_Vl;
    const float scale = (z == 0) ? 0.125f : 1.0f;

    float acc[2][8][4];
#pragma unroll
    for (int mi = 0; mi < 2; mi++)
#pragma unroll
        for (int ni = 0; ni < 8; ni++)
#pragma unroll
            for (int r = 0; r < 4; r++) acc[mi][ni][r] = 0.0f;

    gemm_mainloop(smem_u, tid, lane, wm, wn,
                  g_Xh + (size_t)mtile * 64 * DD,
                  g_Xl + (size_t)mtile * 64 * DD,
                  Bh_g + (size_t)ntile * 128 * DD,
                  Bl_g + (size_t)ntile * 128 * DD, acc);

    const int mb = mtile * 64 + wm * 32 + (lane >> 2);
    const int nb0 = ntile * 128 + wn * 64 + (lane & 3) * 2;

#pragma unroll
    for (int mi = 0; mi < 2; mi++)
#pragma unroll
        for (int ni = 0; ni < 8; ni++) {
            int n = nb0 + ni * 8;
            float2 bsv = *(const float2*)(bias + n);
            int hh2 = n >> 6, hd = n & 63;
#pragma unroll
            for (int half = 0; half < 2; half++) {
                int mg = mb + mi * 16 + half * 8;
                float v0 = (acc[mi][ni][half * 2 + 0] + bsv.x) * scale;
                float v1 = (acc[mi][ni][half * 2 + 1] + bsv.y) * scale;
                __nv_bfloat162 hp = __floats2bfloat162_rn(v0, v1);
                __nv_bfloat162 lp = __floats2bfloat162_rn(
                    v0 - __bfloat162float(hp.x), v1 - __bfloat162float(hp.y));
                int bq2 = mg >> 12, sseq = mg & 4095;
                size_t off = ((size_t)(bq2 * HH + hh2) * SS + sseq) * HD + hd;
                *(__nv_bfloat162*)(Ch + off) = hp;
                *(__nv_bfloat162*)(Cl + off) = lp;
            }
        }
}

// ---------------------------------------------------------------------------
// Output projection GEMM. grid (8, 128)
// ---------------------------------------------------------------------------
__global__ void __launch_bounds__(128, 3) gemm_out_kernel(
    const float* __restrict__ bo, float* __restrict__ Cf)
{
    extern __shared__ char smem[];
    const uint32_t smem_u = smem_to_u32(smem);

    const int tid = threadIdx.x, wid = tid >> 5, lane = tid & 31;
    const int mtile = blockIdx.y, ntile = blockIdx.x;
    const int wm = wid & 1, wn = wid >> 1;

    float acc[2][8][4];
#pragma unroll
    for (int mi = 0; mi < 2; mi++)
#pragma unroll
        for (int ni = 0; ni < 8; ni++)
#pragma unroll
            for (int r = 0; r < 4; r++) acc[mi][ni][r] = 0.0f;

    gemm_mainloop(smem_u, tid, lane, wm, wn,
                  g_Ah + (size_t)mtile * 64 * DD,
                  g_Al + (size_t)mtile * 64 * DD,
                  g_Wht + 3 * (size_t)DD * DD + (size_t)ntile * 128 * DD,
                  g_Wlt + 3 * (size_t)DD * DD + (size_t)ntile * 128 * DD, acc);

    const int mb = mtile * 64 + wm * 32 + (lane >> 2);
    const int nb0 = ntile * 128 + wn * 64 + (lane & 3) * 2;

#pragma unroll
    for (int mi = 0; mi < 2; mi++)
#pragma unroll
        for (int ni = 0; ni < 8; ni++) {
            int n = nb0 + ni * 8;
            float2 bsv = *(const float2*)(bo + n);
#pragma unroll
            for (int half = 0; half < 2; half++) {
                int m = mb + mi * 16 + half * 8;
                float2 o;
                o.x = acc[mi][ni][half * 2 + 0] + bsv.x;
                o.y = acc[mi][ni][half * 2 + 1] + bsv.y;
                *(float2*)(Cf + (size_t)m * DD + n) = o;
            }
        }
}

// ---------------------------------------------------------------------------
// Flash attention, TQ=64, 128 threads, 2 CTAs/SM for softmax/MMA overlap.
// ---------------------------------------------------------------------------
#define TQ 64
#define TK 64
#define QST 72
#define QTILE_B (64 * QST * 2)     // 9216
#define KTILE_B (64 * QST * 2)     // 9216
#define ATTN_SMEM (2 * QTILE_B + 2 * 4 * KTILE_B)  // 92160

__global__ void __launch_bounds__(128, 2) attn_mma_kernel()
{
    extern __shared__ char smem[];
    const uint32_t smem_u = smem_to_u32(smem);
    const uint32_t sQh = smem_u;
    const uint32_t sQl = smem_u + QTILE_B;
    const uint32_t sBuf = smem_u + 2 * QTILE_B;

    const int tid = threadIdx.x, wid = tid >> 5, lane = tid & 31;
    const int b = blockIdx.z, h = blockIdx.y;
    const int q0 = blockIdx.x * TQ;
    const size_t bhoff = (size_t)(b * HH + h) * SS * HD;

    // Stage Q (hi + lo): 2 arrays x 64 rows x 8 groups = 1024 segs
    {
        const __nv_bfloat16* qsrc[2] = { g_Qh + bhoff + (size_t)q0 * HD,
                                         g_Ql + bhoff + (size_t)q0 * HD };
#pragma unroll
        for (int i = 0; i < 8; i++) {
            int seg = tid + i * 128;
            int arr = seg >> 9, rem = seg & 511;
            int row = rem >> 3, g = rem & 7;
            cp_async16(smem_u + (uint32_t)arr * QTILE_B + (uint32_t)(row * QST + g * 8) * 2,
                       qsrc[arr] + (size_t)row * HD + g * 8);
        }
    }
    CP_COMMIT();

    const __nv_bfloat16* kvsrc[4] = { g_Kh + bhoff, g_Kl + bhoff,
                                      g_Vh + bhoff, g_Vl + bhoff };
    auto issue_kv = [&](int t) {
        const uint32_t boff = sBuf + (uint32_t)(t & 1) * (4 * KTILE_B);
#pragma unroll
        for (int i = 0; i < 16; i++) {
            int seg = tid + i * 128;
            int arr = seg >> 9;
            int rem = seg & 511;
            int row = rem >> 3, g = rem & 7;
            cp_async16(boff + (uint32_t)arr * KTILE_B + (uint32_t)(row * QST + g * 8) * 2,
                       kvsrc[arr] + (size_t)(t * TK + row) * HD + g * 8);
        }
    };
    issue_kv(0); CP_COMMIT();

    CP_WAIT1();
    __syncthreads();

    uint32_t qh[4][4], ql[4][4];
    {
        const int a_row = wid * 16 + (lane & 15);
        const int a_kof = (lane >> 4) * 8;
#pragma unroll
        for (int k = 0; k < 4; k++) {
            uint32_t ao = (uint32_t)(a_row * QST + k * 16 + a_kof) * 2;
            ldsm_x4(qh[k][0], qh[k][1], qh[k][2], qh[k][3], sQh + ao);
            ldsm_x4(ql[k][0], ql[k][1], ql[k][2], ql[k][3], sQl + ao);
        }
    }

    float m0 = -1e30f, m1 = -1e30f, l0 = 0.0f, l1 = 0.0f;
    float o[8][4];
#pragma unroll
    for (int nb = 0; nb < 8; nb++)
#pragma unroll
        for (int r = 0; r < 4; r++) o[nb][r] = 0.0f;

    const int b_row = (lane & 7) + (lane >> 4) * 8;
    const int b_kof = ((lane >> 3) & 1) * 8;
    const int v_row = (lane & 15);
    const int v_col = (lane >> 4) * 8;

    for (int t = 0; t < SS / TK; t++) {
        CP_WAIT0();
        __syncthreads();
        if (t < SS / TK - 1) { issue_kv(t + 1); CP_COMMIT(); }

        const uint32_t boff = sBuf + (uint32_t)(t & 1) * (4 * KTILE_B);
        const uint32_t tKh = boff, tKl = boff + KTILE_B;
        const uint32_t tVh = boff + 2 * KTILE_B, tVl = boff + 3 * KTILE_B;

        // ---- S = Q K^T (3-term split) ----
        float s[8][4];
#pragma unroll
        for (int nb = 0; nb < 8; nb++)
#pragma unroll
            for (int r = 0; r < 4; r++) s[nb][r] = 0.0f;

#pragma unroll
        for (int k = 0; k < 4; k++) {
            uint32_t kh[8][2], kl[8][2];
#pragma unroll
            for (int p = 0; p < 4; p++) {
                uint32_t bo = (uint32_t)((p * 16 + b_row) * QST + k * 16 + b_kof) * 2;
                ldsm_x4(kh[2 * p][0], kh[2 * p][1], kh[2 * p + 1][0], kh[2 * p + 1][1], tKh + bo);
                ldsm_x4(kl[2 * p][0], kl[2 * p][1], kl[2 * p + 1][0], kl[2 * p + 1][1], tKl + bo);
            }
#pragma unroll
            for (int nb = 0; nb < 8; nb++) {
                mma16816(s[nb], qh[k], kh[nb]);
                mma16816(s[nb], qh[k], kl[nb]);
                mma16816(s[nb], ql[k], kh[nb]);
            }
        }

        // ---- online softmax ----
        float rm0 = -1e30f, rm1 = -1e30f;
#pragma unroll
        for (int nb = 0; nb < 8; nb++) {
            rm0 = fmaxf(rm0, fmaxf(s[nb][0], s[nb][1]));
            rm1 = fmaxf(rm1, fmaxf(s[nb][2], s[nb][3]));
        }
        rm0 = fmaxf(rm0, __shfl_xor_sync(0xffffffffu, rm0, 1));
        rm0 = fmaxf(rm0, __shfl_xor_sync(0xffffffffu, rm0, 2));
        rm1 = fmaxf(rm1, __shfl_xor_sync(0xffffffffu, rm1, 1));
        rm1 = fmaxf(rm1, __shfl_xor_sync(0xffffffffu, rm1, 2));

        float mn0 = fmaxf(m0, rm0), mn1 = fmaxf(m1, rm1);
        float al0 = __expf(m0 - mn0), al1 = __expf(m1 - mn1);
        m0 = mn0; m1 = mn1;

        float rs0 = 0.0f, rs1 = 0.0f;
#pragma unroll
        for (int nb = 0; nb < 8; nb++) {
            s[nb][0] = __expf(s[nb][0] - mn0);
            s[nb][1] = __expf(s[nb][1] - mn0);
            s[nb][2] = __expf(s[nb][2] - mn1);
            s[nb][3] = __expf(s[nb][3] - mn1);
            rs0 += s[nb][0] + s[nb][1];
            rs1 += s[nb][2] + s[nb][3];
        }
        rs0 += __shfl_xor_sync(0xffffffffu, rs0, 1);
        rs0 += __shfl_xor_sync(0xffffffffu, rs0, 2);
        rs1 += __shfl_xor_sync(0xffffffffu, rs1, 1);
        rs1 += __shfl_xor_sync(0xffffffffu, rs1, 2);
        l0 = l0 * al0 + rs0;
        l1 = l1 * al1 + rs1;
#pragma unroll
        for (int nb = 0; nb < 8; nb++) {
            o[nb][0] *= al0; o[nb][1] *= al0;
            o[nb][2] *= al1; o[nb][3] *= al1;
        }

        // ---- pack P into A-fragments (hi + lo) ----
        uint32_t ph[4][4], pl[4][4];
#pragma unroll
        for (int j = 0; j < 4; j++) {
            float pv[4][2] = {
                { s[2 * j][0],     s[2 * j][1]     },
                { s[2 * j][2],     s[2 * j][3]     },
                { s[2 * j + 1][0], s[2 * j + 1][1] },
                { s[2 * j + 1][2], s[2 * j + 1][3] } };
#pragma unroll
            for (int r = 0; r < 4; r++) {
                __nv_bfloat162 hp = __floats2bfloat162_rn(pv[r][0], pv[r][1]);
                __nv_bfloat162 lp = __floats2bfloat162_rn(
                    pv[r][0] - __bfloat162float(hp.x),
                    pv[r][1] - __bfloat162float(hp.y));
                ph[j][r] = *reinterpret_cast<uint32_t*>(&hp);
                pl[j][r] = *reinterpret_cast<uint32_t*>(&lp);
            }
        }

        // ---- O += P V (3-term split) ----
#pragma unroll
        for (int j = 0; j < 4; j++) {
            uint32_t vh[8][2], vl[8][2];
#pragma unroll
            for (int p = 0; p < 4; p++) {
                uint32_t vo = (uint32_t)((j * 16 + v_row) * QST + p * 16 + v_col) * 2;
                ldsm_x4t(vh[2 * p][0], vh[2 * p][1], vh[2 * p + 1][0], vh[2 * p + 1][1], tVh + vo);
                ldsm_x4t(vl[2 * p][0], vl[2 * p][1], vl[2 * p + 1][0], vl[2 * p + 1][1], tVl + vo);
            }
#pragma unroll
            for (int nb = 0; nb < 8; nb++) {
                mma16816(o[nb], ph[j], vh[nb]);
                mma16816(o[nb], ph[j], vl[nb]);
                mma16816(o[nb], pl[j], vh[nb]);
            }
        }
    }

    // ---- epilogue ----
    const float inv0 = 1.0f / l0, inv1 = 1.0f / l1;
    const int qrow = q0 + wid * 16 + (lane >> 2);
    const size_t mrow0 = (size_t)(b * SS + qrow);
    const size_t mrow1 = mrow0 + 8;
    const int colb = h * HD + (lane & 3) * 2;
#pragma unroll
    for (int nb = 0; nb < 8; nb++) {
        int col = colb + nb * 8;
        float x0 = o[nb][0] * inv0, x1 = o[nb][1] * inv0;
        float x2 = o[nb][2] * inv1, x3 = o[nb][3] * inv1;
        __nv_bfloat162 h0 = __floats2bfloat162_rn(x0, x1);
        __nv_bfloat162 g0 = __floats2bfloat162_rn(
            x0 - __bfloat162float(h0.x), x1 - __bfloat162float(h0.y));
        __nv_bfloat162 h1 = __floats2bfloat162_rn(x2, x3);
        __nv_bfloat162 g1 = __floats2bfloat162_rn(
            x2 - __bfloat162float(h1.x), x3 - __bfloat162float(h1.y));
        *(__nv_bfloat162*)(g_Ah + mrow0 * DD + col) = h0;
        *(__nv_bfloat162*)(g_Al + mrow0 * DD + col) = g0;
        *(__nv_bfloat162*)(g_Ah + mrow1 * DD + col) = h1;
        *(__nv_bfloat162*)(g_Al + mrow1 * DD + col) = g1;
    }
}

// ---------------------------------------------------------------------------
// Launch
// ---------------------------------------------------------------------------
extern "C" void kernel_launch(void* const* d_in, const int* in_sizes, int n_in,
                              void* d_out, int out_size)
{
    (void)in_sizes; (void)n_in; (void)out_size;
    const float* X  = (const float*)d_in[0];
    const float* Wq = (const float*)d_in[1];
    const float* bq = (const float*)d_in[2];
    const float* Wk = (const float*)d_in[3];
    const float* bk = (const float*)d_in[4];
    const float* Wv = (const float*)d_in[5];
    const float* bv = (const float*)d_in[6];
    const float* Wo = (const float*)d_in[7];
    const float* bo = (const float*)d_in[8];
    float* out = (float*)d_out;

    __nv_bfloat16* pXh;
    __nv_bfloat16* pXl;
    cudaGetSymbolAddress((void**)&pXh, g_Xh);
    cudaGetSymbolAddress((void**)&pXl, g_Xl);

    cudaFuncSetAttribute(gemm_qkv_kernel,
                         cudaFuncAttributeMaxDynamicSharedMemorySize, GEMM_SMEM);
    cudaFuncSetAttribute(gemm_out_kernel,
                         cudaFuncAttributeMaxDynamicSharedMemorySize, GEMM_SMEM);
    cudaFuncSetAttribute(attn_mma_kernel,
                         cudaFuncAttributeMaxDynamicSharedMemorySize, ATTN_SMEM);

    xsplit_kernel<<<MM * DD / 4 / 256, 256>>>(X, pXh, pXl);
    dim3 gW(32, 32, 4), bW(32, 8);
    wsplit4_kernel<<<gW, bW>>>(Wq, Wk, Wv, Wo);

    dim3 gQKV(DD / 128, MM / 64, 3);    // (8, 128, 3)
    gemm_qkv_kernel<<<gQKV, 128, GEMM_SMEM>>>(bq, bk, bv);

    dim3 gattn(SS / TQ, HH, BB);        // (64, 16, 2)
    attn_mma_kernel<<<gattn, 128, ATTN_SMEM>>>();

    dim3 gO(DD / 128, MM / 64);         // (8, 128)
    gemm_out_kernel<<<gO, 128, GEMM_SMEM>>>(bo, out);
}

// round 7
// speedup vs baseline: 3.1872x; 1.0120x over previous
#include <cuda_runtime.h>
#include <cuda_bf16.h>
#include <cstdint>
#include <math.h>

// Problem constants
#define BB 2
#define SS 4096
#define DD 1024
#define HH 16
#define HD 64
#define MM (BB * SS)   // 8192

// ---------------------------------------------------------------------------
// Scratch (device globals)
// ---------------------------------------------------------------------------
__device__ __nv_bfloat16 g_Xh[MM * DD];
__device__ __nv_bfloat16 g_Xl[MM * DD];
__device__ __nv_bfloat16 g_Wht[4 * DD * DD];
__device__ __nv_bfloat16 g_Wlt[4 * DD * DD];
__device__ __nv_bfloat16 g_Qh[MM * DD];
__device__ __nv_bfloat16 g_Ql[MM * DD];
__device__ __nv_bfloat16 g_Kh[MM * DD];
__device__ __nv_bfloat16 g_Kl[MM * DD];
__device__ __nv_bfloat16 g_Vh[MM * DD];
__device__ __nv_bfloat16 g_Vl[MM * DD];
__device__ __nv_bfloat16 g_Ah[MM * DD];
__device__ __nv_bfloat16 g_Al[MM * DD];

// ---------------------------------------------------------------------------
// PTX helpers
// ---------------------------------------------------------------------------
__device__ __forceinline__ uint32_t smem_to_u32(const void* p) {
    uint32_t a;
    asm("{ .reg .u64 t; cvta.to.shared.u64 t, %1; cvt.u32.u64 %0, t; }"
        : "=r"(a) : "l"(p));
    return a;
}

__device__ __forceinline__ void cp_async16(uint32_t dst, const void* src) {
    asm volatile("cp.async.cg.shared.global [%0], [%1], 16;"
                 :: "r"(dst), "l"(src));
}
#define CP_COMMIT() asm volatile("cp.async.commit_group;" ::: "memory")
#define CP_WAIT1()  asm volatile("cp.async.wait_group 1;" ::: "memory")
#define CP_WAIT0()  asm volatile("cp.async.wait_group 0;" ::: "memory")

__device__ __forceinline__ void ldsm_x4(uint32_t& r0, uint32_t& r1,
                                        uint32_t& r2, uint32_t& r3, uint32_t addr) {
    asm volatile("ldmatrix.sync.aligned.m8n8.x4.shared.b16 {%0,%1,%2,%3}, [%4];"
                 : "=r"(r0), "=r"(r1), "=r"(r2), "=r"(r3) : "r"(addr));
}

__device__ __forceinline__ void ldsm_x4t(uint32_t& r0, uint32_t& r1,
                                         uint32_t& r2, uint32_t& r3, uint32_t addr) {
    asm volatile("ldmatrix.sync.aligned.m8n8.x4.trans.shared.b16 {%0,%1,%2,%3}, [%4];"
                 : "=r"(r0), "=r"(r1), "=r"(r2), "=r"(r3) : "r"(addr));
}

__device__ __forceinline__ void mma16816(float* c, const uint32_t* a, const uint32_t* b) {
    asm volatile(
        "mma.sync.aligned.m16n8k16.row.col.f32.bf16.bf16.f32 "
        "{%0,%1,%2,%3}, {%4,%5,%6,%7}, {%8,%9}, {%0,%1,%2,%3};"
        : "+f"(c[0]), "+f"(c[1]), "+f"(c[2]), "+f"(c[3])
        : "r"(a[0]), "r"(a[1]), "r"(a[2]), "r"(a[3]), "r"(b[0]), "r"(b[1]));
}

// ---------------------------------------------------------------------------
// hi/lo bf16 split of X
// ---------------------------------------------------------------------------
__global__ void __launch_bounds__(256) xsplit_kernel(
    const float* __restrict__ X,
    __nv_bfloat16* __restrict__ Xh, __nv_bfloat16* __restrict__ Xl)
{
    int i = (blockIdx.x * 256 + threadIdx.x) * 4;
    float4 v = *(const float4*)(X + i);
    __nv_bfloat162 hp0 = __floats2bfloat162_rn(v.x, v.y);
    __nv_bfloat162 hp1 = __floats2bfloat162_rn(v.z, v.w);
    __nv_bfloat162 lp0 = __floats2bfloat162_rn(v.x - __bfloat162float(hp0.x),
                                               v.y - __bfloat162float(hp0.y));
    __nv_bfloat162 lp1 = __floats2bfloat162_rn(v.z - __bfloat162float(hp1.x),
                                               v.w - __bfloat162float(hp1.y));
    *(__nv_bfloat162*)(Xh + i)     = hp0;
    *(__nv_bfloat162*)(Xh + i + 2) = hp1;
    *(__nv_bfloat162*)(Xl + i)     = lp0;
    *(__nv_bfloat162*)(Xl + i + 2) = lp1;
}

// ---------------------------------------------------------------------------
// Transpose + split all 4 weights
// ---------------------------------------------------------------------------
__global__ void __launch_bounds__(256) wsplit4_kernel(
    const float* __restrict__ W0, const float* __restrict__ W1,
    const float* __restrict__ W2, const float* __restrict__ W3)
{
    __shared__ float t[32][33];
    const int z = blockIdx.z;
    const float* W = (z == 0) ? W0 : (z == 1) ? W1 : (z == 2) ? W2 : W3;
    __nv_bfloat16* Wht = g_Wht + (size_t)z * DD * DD;
    __nv_bfloat16* Wlt = g_Wlt + (size_t)z * DD * DD;

    int tx = threadIdx.x, ty = threadIdx.y;
    int n0 = blockIdx.x * 32, k0 = blockIdx.y * 32;
#pragma unroll
    for (int i = 0; i < 4; i++)
        t[ty + i * 8][tx] = W[(size_t)(k0 + ty + i * 8) * DD + n0 + tx];
    __syncthreads();
#pragma unroll
    for (int i = 0; i < 4; i++) {
        float v = t[tx][ty + i * 8];
        __nv_bfloat16 h = __float2bfloat16_rn(v);
        __nv_bfloat16 l = __float2bfloat16_rn(v - __bfloat162float(h));
        size_t idx = (size_t)(n0 + ty + i * 8) * DD + k0 + tx;
        Wht[idx] = h;
        Wlt[idx] = l;
    }
}

// ---------------------------------------------------------------------------
// GEMM mainloop (64x128 CTA tile, 128 threads, KC=32, double-buffered)
//   Term-major MMA issue: all independent accumulators between dependent pairs.
// ---------------------------------------------------------------------------
#define KC 32
#define GSTRIDE 40
#define TILE_A (64 * GSTRIDE * 2)
#define TILE_BB (128 * GSTRIDE * 2)
#define BUF_B  (2 * TILE_A + 2 * TILE_BB)
#define GEMM_SMEM (2 * BUF_B)

__device__ __forceinline__ void gemm_mainloop(
    uint32_t smem_u, int tid, int lane, int wm, int wn,
    const __nv_bfloat16* ah_g, const __nv_bfloat16* al_g,
    const __nv_bfloat16* bh_g, const __nv_bfloat16* bl_g,
    float acc[2][8][4])
{
    auto issue_chunk = [&](int c) {
        const uint32_t boff = smem_u + (uint32_t)(c & 1) * BUF_B;
#pragma unroll
        for (int i = 0; i < 4; i++) {
            int seg = tid + i * 128;
            int t = seg >> 8;
            int rem = seg & 255;
            int row = rem >> 2, g = rem & 3;
            const __nv_bfloat16* src = t ? al_g : ah_g;
            cp_async16(boff + (uint32_t)t * TILE_A
                       + (uint32_t)(row * GSTRIDE + g * 8) * 2,
                       src + (size_t)row * DD + c * KC + g * 8);
        }
#pragma unroll
        for (int i = 0; i < 8; i++) {
            int seg = tid + i * 128;
            int t = seg >> 9;
            int rem = seg & 511;
            int row = rem >> 2, g = rem & 3;
            const __nv_bfloat16* src = t ? bl_g : bh_g;
            cp_async16(boff + 2 * TILE_A + (uint32_t)t * TILE_BB
                       + (uint32_t)(row * GSTRIDE + g * 8) * 2,
                       src + (size_t)row * DD + c * KC + g * 8);
        }
    };

    const int a_row = wm * 32 + (lane & 15);
    const int a_kof = (lane >> 4) * 8;
    const int b_row = wn * 64 + (lane & 7) + (lane >> 4) * 8;
    const int b_kof = ((lane >> 3) & 1) * 8;

    issue_chunk(0);
    CP_COMMIT();

    for (int c = 0; c < 32; c++) {
        CP_WAIT0();
        __syncthreads();
        if (c < 31) { issue_chunk(c + 1); CP_COMMIT(); }

        const uint32_t boff = smem_u + (uint32_t)(c & 1) * BUF_B;
        const uint32_t tAh = boff;
        const uint32_t tAl = boff + TILE_A;
        const uint32_t tBh = boff + 2 * TILE_A;
        const uint32_t tBl = boff + 2 * TILE_A + TILE_BB;

#pragma unroll
        for (int kb = 0; kb < KC; kb += 16) {
            uint32_t ah[2][4], al[2][4], bh[8][2], bl[8][2];
#pragma unroll
            for (int mi = 0; mi < 2; mi++) {
                uint32_t ao = (uint32_t)((a_row + mi * 16) * GSTRIDE + kb + a_kof) * 2;
                ldsm_x4(ah[mi][0], ah[mi][1], ah[mi][2], ah[mi][3], tAh + ao);
                ldsm_x4(al[mi][0], al[mi][1], al[mi][2], al[mi][3], tAl + ao);
            }
#pragma unroll
            for (int p = 0; p < 4; p++) {
                uint32_t bo = (uint32_t)((p * 16 + b_row) * GSTRIDE + kb + b_kof) * 2;
                ldsm_x4(bh[2 * p][0], bh[2 * p][1], bh[2 * p + 1][0], bh[2 * p + 1][1], tBh + bo);
                ldsm_x4(bl[2 * p][0], bl[2 * p][1], bl[2 * p + 1][0], bl[2 * p + 1][1], tBl + bo);
            }
            // Term-major: 16 independent MMAs between dependent reuses
#pragma unroll
            for (int mi = 0; mi < 2; mi++)
#pragma unroll
                for (int ni = 0; ni < 8; ni++)
                    mma16816(acc[mi][ni], ah[mi], bh[ni]);   // hh
#pragma unroll
            for (int mi = 0; mi < 2; mi++)
#pragma unroll
                for (int ni = 0; ni < 8; ni++)
                    mma16816(acc[mi][ni], ah[mi], bl[ni]);   // hl
#pragma unroll
            for (int mi = 0; mi < 2; mi++)
#pragma unroll
                for (int ni = 0; ni < 8; ni++)
                    mma16816(acc[mi][ni], al[mi], bh[ni]);   // lh
        }
        __syncthreads();
    }
}

// ---------------------------------------------------------------------------
// Fused QKV projection GEMM. grid (8, 128, 3)
// ---------------------------------------------------------------------------
__global__ void __launch_bounds__(128, 3) gemm_qkv_kernel(
    const float* __restrict__ bq, const float* __restrict__ bk,
    const float* __restrict__ bv)
{
    extern __shared__ char smem[];
    const uint32_t smem_u = smem_to_u32(smem);

    const int tid = threadIdx.x, wid = tid >> 5, lane = tid & 31;
    const int mtile = blockIdx.y, ntile = blockIdx.x, z = blockIdx.z;
    const int wm = wid & 1, wn = wid >> 1;

    const __nv_bfloat16* Bh_g = g_Wht + (size_t)z * DD * DD;
    const __nv_bfloat16* Bl_g = g_Wlt + (size_t)z * DD * DD;
    const float* bias = (z == 0) ? bq : (z == 1) ? bk : bv;
    __nv_bfloat16* Ch = (z == 0) ? g_Qh : (z == 1) ? g_Kh : g_Vh;
    __nv_bfloat16* Cl = (z == 0) ? g_Ql : (z == 1) ? g_Kl : g_Vl;
    const float scale = (z == 0) ? 0.125f : 1.0f;

    float acc[2][8][4];
#pragma unroll
    for (int mi = 0; mi < 2; mi++)
#pragma unroll
        for (int ni = 0; ni < 8; ni++)
#pragma unroll
            for (int r = 0; r < 4; r++) acc[mi][ni][r] = 0.0f;

    gemm_mainloop(smem_u, tid, lane, wm, wn,
                  g_Xh + (size_t)mtile * 64 * DD,
                  g_Xl + (size_t)mtile * 64 * DD,
                  Bh_g + (size_t)ntile * 128 * DD,
                  Bl_g + (size_t)ntile * 128 * DD, acc);

    const int mb = mtile * 64 + wm * 32 + (lane >> 2);
    const int nb0 = ntile * 128 + wn * 64 + (lane & 3) * 2;

#pragma unroll
    for (int mi = 0; mi < 2; mi++)
#pragma unroll
        for (int ni = 0; ni < 8; ni++) {
            int n = nb0 + ni * 8;
            float2 bsv = *(const float2*)(bias + n);
            int hh2 = n >> 6, hd = n & 63;
#pragma unroll
            for (int half = 0; half < 2; half++) {
                int mg = mb + mi * 16 + half * 8;
                float v0 = (acc[mi][ni][half * 2 + 0] + bsv.x) * scale;
                float v1 = (acc[mi][ni][half * 2 + 1] + bsv.y) * scale;
                __nv_bfloat162 hp = __floats2bfloat162_rn(v0, v1);
                __nv_bfloat162 lp = __floats2bfloat162_rn(
                    v0 - __bfloat162float(hp.x), v1 - __bfloat162float(hp.y));
                int bq2 = mg >> 12, sseq = mg & 4095;
                size_t off = ((size_t)(bq2 * HH + hh2) * SS + sseq) * HD + hd;
                *(__nv_bfloat162*)(Ch + off) = hp;
                *(__nv_bfloat162*)(Cl + off) = lp;
            }
        }
}

// ---------------------------------------------------------------------------
// Output projection GEMM. grid (8, 128)
// ---------------------------------------------------------------------------
__global__ void __launch_bounds__(128, 3) gemm_out_kernel(
    const float* __restrict__ bo, float* __restrict__ Cf)
{
    extern __shared__ char smem[];
    const uint32_t smem_u = smem_to_u32(smem);

    const int tid = threadIdx.x, wid = tid >> 5, lane = tid & 31;
    const int mtile = blockIdx.y, ntile = blockIdx.x;
    const int wm = wid & 1, wn = wid >> 1;

    float acc[2][8][4];
#pragma unroll
    for (int mi = 0; mi < 2; mi++)
#pragma unroll
        for (int ni = 0; ni < 8; ni++)
#pragma unroll
            for (int r = 0; r < 4; r++) acc[mi][ni][r] = 0.0f;

    gemm_mainloop(smem_u, tid, lane, wm, wn,
                  g_Ah + (size_t)mtile * 64 * DD,
                  g_Al + (size_t)mtile * 64 * DD,
                  g_Wht + 3 * (size_t)DD * DD + (size_t)ntile * 128 * DD,
                  g_Wlt + 3 * (size_t)DD * DD + (size_t)ntile * 128 * DD, acc);

    const int mb = mtile * 64 + wm * 32 + (lane >> 2);
    const int nb0 = ntile * 128 + wn * 64 + (lane & 3) * 2;

#pragma unroll
    for (int mi = 0; mi < 2; mi++)
#pragma unroll
        for (int ni = 0; ni < 8; ni++) {
            int n = nb0 + ni * 8;
            float2 bsv = *(const float2*)(bo + n);
#pragma unroll
            for (int half = 0; half < 2; half++) {
                int m = mb + mi * 16 + half * 8;
                float2 o;
                o.x = acc[mi][ni][half * 2 + 0] + bsv.x;
                o.y = acc[mi][ni][half * 2 + 1] + bsv.y;
                *(float2*)(Cf + (size_t)m * DD + n) = o;
            }
        }
}

// ---------------------------------------------------------------------------
// Flash attention, TQ=64, 128 threads, 2 CTAs/SM. Term-major MMA issue.
// ---------------------------------------------------------------------------
#define TQ 64
#define TK 64
#define QST 72
#define QTILE_B (64 * QST * 2)
#define KTILE_B (64 * QST * 2)
#define ATTN_SMEM (2 * QTILE_B + 2 * 4 * KTILE_B)  // 92160

__global__ void __launch_bounds__(128, 2) attn_mma_kernel()
{
    extern __shared__ char smem[];
    const uint32_t smem_u = smem_to_u32(smem);
    const uint32_t sQh = smem_u;
    const uint32_t sQl = smem_u + QTILE_B;
    const uint32_t sBuf = smem_u + 2 * QTILE_B;

    const int tid = threadIdx.x, wid = tid >> 5, lane = tid & 31;
    const int b = blockIdx.z, h = blockIdx.y;
    const int q0 = blockIdx.x * TQ;
    const size_t bhoff = (size_t)(b * HH + h) * SS * HD;

    {
        const __nv_bfloat16* qsrc[2] = { g_Qh + bhoff + (size_t)q0 * HD,
                                         g_Ql + bhoff + (size_t)q0 * HD };
#pragma unroll
        for (int i = 0; i < 8; i++) {
            int seg = tid + i * 128;
            int arr = seg >> 9, rem = seg & 511;
            int row = rem >> 3, g = rem & 7;
            cp_async16(smem_u + (uint32_t)arr * QTILE_B + (uint32_t)(row * QST + g * 8) * 2,
                       qsrc[arr] + (size_t)row * HD + g * 8);
        }
    }
    CP_COMMIT();

    const __nv_bfloat16* kvsrc[4] = { g_Kh + bhoff, g_Kl + bhoff,
                                      g_Vh + bhoff, g_Vl + bhoff };
    auto issue_kv = [&](int t) {
        const uint32_t boff = sBuf + (uint32_t)(t & 1) * (4 * KTILE_B);
#pragma unroll
        for (int i = 0; i < 16; i++) {
            int seg = tid + i * 128;
            int arr = seg >> 9;
            int rem = seg & 511;
            int row = rem >> 3, g = rem & 7;
            cp_async16(boff + (uint32_t)arr * KTILE_B + (uint32_t)(row * QST + g * 8) * 2,
                       kvsrc[arr] + (size_t)(t * TK + row) * HD + g * 8);
        }
    };
    issue_kv(0); CP_COMMIT();

    CP_WAIT1();
    __syncthreads();

    uint32_t qh[4][4], ql[4][4];
    {
        const int a_row = wid * 16 + (lane & 15);
        const int a_kof = (lane >> 4) * 8;
#pragma unroll
        for (int k = 0; k < 4; k++) {
            uint32_t ao = (uint32_t)(a_row * QST + k * 16 + a_kof) * 2;
            ldsm_x4(qh[k][0], qh[k][1], qh[k][2], qh[k][3], sQh + ao);
            ldsm_x4(ql[k][0], ql[k][1], ql[k][2], ql[k][3], sQl + ao);
        }
    }

    float m0 = -1e30f, m1 = -1e30f, l0 = 0.0f, l1 = 0.0f;
    float o[8][4];
#pragma unroll
    for (int nb = 0; nb < 8; nb++)
#pragma unroll
        for (int r = 0; r < 4; r++) o[nb][r] = 0.0f;

    const int b_row = (lane & 7) + (lane >> 4) * 8;
    const int b_kof = ((lane >> 3) & 1) * 8;
    const int v_row = (lane & 15);
    const int v_col = (lane >> 4) * 8;

    for (int t = 0; t < SS / TK; t++) {
        CP_WAIT0();
        __syncthreads();
        if (t < SS / TK - 1) { issue_kv(t + 1); CP_COMMIT(); }

        const uint32_t boff = sBuf + (uint32_t)(t & 1) * (4 * KTILE_B);
        const uint32_t tKh = boff, tKl = boff + KTILE_B;
        const uint32_t tVh = boff + 2 * KTILE_B, tVl = boff + 3 * KTILE_B;

        // ---- S = Q K^T (3-term split, term-major issue) ----
        float s[8][4];
#pragma unroll
        for (int nb = 0; nb < 8; nb++)
#pragma unroll
            for (int r = 0; r < 4; r++) s[nb][r] = 0.0f;

#pragma unroll
        for (int k = 0; k < 4; k++) {
            uint32_t kh[8][2], kl[8][2];
#pragma unroll
            for (int p = 0; p < 4; p++) {
                uint32_t bo = (uint32_t)((p * 16 + b_row) * QST + k * 16 + b_kof) * 2;
                ldsm_x4(kh[2 * p][0], kh[2 * p][1], kh[2 * p + 1][0], kh[2 * p + 1][1], tKh + bo);
                ldsm_x4(kl[2 * p][0], kl[2 * p][1], kl[2 * p + 1][0], kl[2 * p + 1][1], tKl + bo);
            }
#pragma unroll
            for (int nb = 0; nb < 8; nb++)
                mma16816(s[nb], qh[k], kh[nb]);   // hh
#pragma unroll
            for (int nb = 0; nb < 8; nb++)
                mma16816(s[nb], qh[k], kl[nb]);   // hl
#pragma unroll
            for (int nb = 0; nb < 8; nb++)
                mma16816(s[nb], ql[k], kh[nb]);   // lh
        }

        // ---- online softmax ----
        float rm0 = -1e30f, rm1 = -1e30f;
#pragma unroll
        for (int nb = 0; nb < 8; nb++) {
            rm0 = fmaxf(rm0, fmaxf(s[nb][0], s[nb][1]));
            rm1 = fmaxf(rm1, fmaxf(s[nb][2], s[nb][3]));
        }
        rm0 = fmaxf(rm0, __shfl_xor_sync(0xffffffffu, rm0, 1));
        rm0 = fmaxf(rm0, __shfl_xor_sync(0xffffffffu, rm0, 2));
        rm1 = fmaxf(rm1, __shfl_xor_sync(0xffffffffu, rm1, 1));
        rm1 = fmaxf(rm1, __shfl_xor_sync(0xffffffffu, rm1, 2));

        float mn0 = fmaxf(m0, rm0), mn1 = fmaxf(m1, rm1);
        float al0 = __expf(m0 - mn0), al1 = __expf(m1 - mn1);
        m0 = mn0; m1 = mn1;

        float rs0 = 0.0f, rs1 = 0.0f;
#pragma unroll
        for (int nb = 0; nb < 8; nb++) {
            s[nb][0] = __expf(s[nb][0] - mn0);
            s[nb][1] = __expf(s[nb][1] - mn0);
            s[nb][2] = __expf(s[nb][2] - mn1);
            s[nb][3] = __expf(s[nb][3] - mn1);
            rs0 += s[nb][0] + s[nb][1];
            rs1 += s[nb][2] + s[nb][3];
        }
        rs0 += __shfl_xor_sync(0xffffffffu, rs0, 1);
        rs0 += __shfl_xor_sync(0xffffffffu, rs0, 2);
        rs1 += __shfl_xor_sync(0xffffffffu, rs1, 1);
        rs1 += __shfl_xor_sync(0xffffffffu, rs1, 2);
        l0 = l0 * al0 + rs0;
        l1 = l1 * al1 + rs1;
#pragma unroll
        for (int nb = 0; nb < 8; nb++) {
            o[nb][0] *= al0; o[nb][1] *= al0;
            o[nb][2] *= al1; o[nb][3] *= al1;
        }

        // ---- pack P into A-fragments (hi + lo) ----
        uint32_t ph[4][4], pl[4][4];
#pragma unroll
        for (int j = 0; j < 4; j++) {
            float pv[4][2] = {
                { s[2 * j][0],     s[2 * j][1]     },
                { s[2 * j][2],     s[2 * j][3]     },
                { s[2 * j + 1][0], s[2 * j + 1][1] },
                { s[2 * j + 1][2], s[2 * j + 1][3] } };
#pragma unroll
            for (int r = 0; r < 4; r++) {
                __nv_bfloat162 hp = __floats2bfloat162_rn(pv[r][0], pv[r][1]);
                __nv_bfloat162 lp = __floats2bfloat162_rn(
                    pv[r][0] - __bfloat162float(hp.x),
                    pv[r][1] - __bfloat162float(hp.y));
                ph[j][r] = *reinterpret_cast<uint32_t*>(&hp);
                pl[j][r] = *reinterpret_cast<uint32_t*>(&lp);
            }
        }

        // ---- O += P V (3-term split, term-major issue) ----
#pragma unroll
        for (int j = 0; j < 4; j++) {
            uint32_t vh[8][2], vl[8][2];
#pragma unroll
            for (int p = 0; p < 4; p++) {
                uint32_t vo = (uint32_t)((j * 16 + v_row) * QST + p * 16 + v_col) * 2;
                ldsm_x4t(vh[2 * p][0], vh[2 * p][1], vh[2 * p + 1][0], vh[2 * p + 1][1], tVh + vo);
                ldsm_x4t(vl[2 * p][0], vl[2 * p][1], vl[2 * p + 1][0], vl[2 * p + 1][1], tVl + vo);
            }
#pragma unroll
            for (int nb = 0; nb < 8; nb++)
                mma16816(o[nb], ph[j], vh[nb]);   // hh
#pragma unroll
            for (int nb = 0; nb < 8; nb++)
                mma16816(o[nb], ph[j], vl[nb]);   // hl
#pragma unroll
            for (int nb = 0; nb < 8; nb++)
                mma16816(o[nb], pl[j], vh[nb]);   // lh
        }
    }

    // ---- epilogue ----
    const float inv0 = 1.0f / l0, inv1 = 1.0f / l1;
    const int qrow = q0 + wid * 16 + (lane >> 2);
    const size_t mrow0 = (size_t)(b * SS + qrow);
    const size_t mrow1 = mrow0 + 8;
    const int colb = h * HD + (lane & 3) * 2;
#pragma unroll
    for (int nb = 0; nb < 8; nb++) {
        int col = colb + nb * 8;
        float x0 = o[nb][0] * inv0, x1 = o[nb][1] * inv0;
        float x2 = o[nb][2] * inv1, x3 = o[nb][3] * inv1;
        __nv_bfloat162 h0 = __floats2bfloat162_rn(x0, x1);
        __nv_bfloat162 g0 = __floats2bfloat162_rn(
            x0 - __bfloat162float(h0.x), x1 - __bfloat162float(h0.y));
        __nv_bfloat162 h1 = __floats2bfloat162_rn(x2, x3);
        __nv_bfloat162 g1 = __floats2bfloat162_rn(
            x2 - __bfloat162float(h1.x), x3 - __bfloat162float(h1.y));
        *(__nv_bfloat162*)(g_Ah + mrow0 * DD + col) = h0;
        *(__nv_bfloat162*)(g_Al + mrow0 * DD + col) = g0;
        *(__nv_bfloat162*)(g_Ah + mrow1 * DD + col) = h1;
        *(__nv_bfloat162*)(g_Al + mrow1 * DD + col) = g1;
    }
}

// ---------------------------------------------------------------------------
// Launch
// ---------------------------------------------------------------------------
extern "C" void kernel_launch(void* const* d_in, const int* in_sizes, int n_in,
                              void* d_out, int out_size)
{
    (void)in_sizes; (void)n_in; (void)out_size;
    const float* X  = (const float*)d_in[0];
    const float* Wq = (const float*)d_in[1];
    const float* bq = (const float*)d_in[2];
    const float* Wk = (const float*)d_in[3];
    const float* bk = (const float*)d_in[4];
    const float* Wv = (const float*)d_in[5];
    const float* bv = (const float*)d_in[6];
    const float* Wo = (const float*)d_in[7];
    const float* bo = (const float*)d_in[8];
    float* out = (float*)d_out;

    __nv_bfloat16* pXh;
    __nv_bfloat16* pXl;
    cudaGetSymbolAddress((void**)&pXh, g_Xh);
    cudaGetSymbolAddress((void**)&pXl, g_Xl);

    cudaFuncSetAttribute(gemm_qkv_kernel,
                         cudaFuncAttributeMaxDynamicSharedMemorySize, GEMM_SMEM);
    cudaFuncSetAttribute(gemm_out_kernel,
                         cudaFuncAttributeMaxDynamicSharedMemorySize, GEMM_SMEM);
    cudaFuncSetAttribute(attn_mma_kernel,
                         cudaFuncAttributeMaxDynamicSharedMemorySize, ATTN_SMEM);

    xsplit_kernel<<<MM * DD / 4 / 256, 256>>>(X, pXh, pXl);
    dim3 gW(32, 32, 4), bW(32, 8);
    wsplit4_kernel<<<gW, bW>>>(Wq, Wk, Wv, Wo);

    dim3 gQKV(DD / 128, MM / 64, 3);
    gemm_qkv_kernel<<<gQKV, 128, GEMM_SMEM>>>(bq, bk, bv);

    dim3 gattn(SS / TQ, HH, BB);
    attn_mma_kernel<<<gattn, 128, ATTN_SMEM>>>();

    dim3 gO(DD / 128, MM / 64);
    gemm_out_kernel<<<gO, 128, GEMM_SMEM>>>(bo, out);
}

// round 8
// speedup vs baseline: 3.3261x; 1.0436x over previous
#include <cuda_runtime.h>
#include <cuda_bf16.h>
#include <cstdint>
#include <math.h>

// Problem constants
#define BB 2
#define SS 4096
#define DD 1024
#define HH 16
#define HD 64
#define MM (BB * SS)   // 8192

// ---------------------------------------------------------------------------
// Scratch (device globals)
// ---------------------------------------------------------------------------
__device__ __nv_bfloat16 g_Xh[MM * DD];
__device__ __nv_bfloat16 g_Xl[MM * DD];
__device__ __nv_bfloat16 g_Wht[4 * DD * DD];
__device__ __nv_bfloat16 g_Wlt[4 * DD * DD];
__device__ __nv_bfloat16 g_Qh[MM * DD];
__device__ __nv_bfloat16 g_Ql[MM * DD];
__device__ __nv_bfloat16 g_Kh[MM * DD];
__device__ __nv_bfloat16 g_Kl[MM * DD];
__device__ __nv_bfloat16 g_Vh[MM * DD];
__device__ __nv_bfloat16 g_Vl[MM * DD];
__device__ __nv_bfloat16 g_Ah[MM * DD];
__device__ __nv_bfloat16 g_Al[MM * DD];

// ---------------------------------------------------------------------------
// PTX helpers
// ---------------------------------------------------------------------------
__device__ __forceinline__ uint32_t smem_to_u32(const void* p) {
    uint32_t a;
    asm("{ .reg .u64 t; cvta.to.shared.u64 t, %1; cvt.u32.u64 %0, t; }"
        : "=r"(a) : "l"(p));
    return a;
}

__device__ __forceinline__ float ex2(float x) {
    float y;
    asm("ex2.approx.f32 %0, %1;" : "=f"(y) : "f"(x));
    return y;
}

__device__ __forceinline__ void cp_async16(uint32_t dst, const void* src) {
    asm volatile("cp.async.cg.shared.global [%0], [%1], 16;"
                 :: "r"(dst), "l"(src));
}
#define CP_COMMIT() asm volatile("cp.async.commit_group;" ::: "memory")
#define CP_WAIT0()  asm volatile("cp.async.wait_group 0;" ::: "memory")

__device__ __forceinline__ void ldsm_x4(uint32_t& r0, uint32_t& r1,
                                        uint32_t& r2, uint32_t& r3, uint32_t addr) {
    asm volatile("ldmatrix.sync.aligned.m8n8.x4.shared.b16 {%0,%1,%2,%3}, [%4];"
                 : "=r"(r0), "=r"(r1), "=r"(r2), "=r"(r3) : "r"(addr));
}

__device__ __forceinline__ void ldsm_x4t(uint32_t& r0, uint32_t& r1,
                                         uint32_t& r2, uint32_t& r3, uint32_t addr) {
    asm volatile("ldmatrix.sync.aligned.m8n8.x4.trans.shared.b16 {%0,%1,%2,%3}, [%4];"
                 : "=r"(r0), "=r"(r1), "=r"(r2), "=r"(r3) : "r"(addr));
}

__device__ __forceinline__ void mma16816(float* c, const uint32_t* a, const uint32_t* b) {
    asm volatile(
        "mma.sync.aligned.m16n8k16.row.col.f32.bf16.bf16.f32 "
        "{%0,%1,%2,%3}, {%4,%5,%6,%7}, {%8,%9}, {%0,%1,%2,%3};"
        : "+f"(c[0]), "+f"(c[1]), "+f"(c[2]), "+f"(c[3])
        : "r"(a[0]), "r"(a[1]), "r"(a[2]), "r"(a[3]), "r"(b[0]), "r"(b[1]));
}

// ---------------------------------------------------------------------------
// hi/lo bf16 split of X
// ---------------------------------------------------------------------------
__global__ void __launch_bounds__(256) xsplit_kernel(
    const float* __restrict__ X,
    __nv_bfloat16* __restrict__ Xh, __nv_bfloat16* __restrict__ Xl)
{
    int i = (blockIdx.x * 256 + threadIdx.x) * 4;
    float4 v = *(const float4*)(X + i);
    __nv_bfloat162 hp0 = __floats2bfloat162_rn(v.x, v.y);
    __nv_bfloat162 hp1 = __floats2bfloat162_rn(v.z, v.w);
    __nv_bfloat162 lp0 = __floats2bfloat162_rn(v.x - __bfloat162float(hp0.x),
                                               v.y - __bfloat162float(hp0.y));
    __nv_bfloat162 lp1 = __floats2bfloat162_rn(v.z - __bfloat162float(hp1.x),
                                               v.w - __bfloat162float(hp1.y));
    *(__nv_bfloat162*)(Xh + i)     = hp0;
    *(__nv_bfloat162*)(Xh + i + 2) = hp1;
    *(__nv_bfloat162*)(Xl + i)     = lp0;
    *(__nv_bfloat162*)(Xl + i + 2) = lp1;
}

// ---------------------------------------------------------------------------
// Transpose + split all 4 weights
// ---------------------------------------------------------------------------
__global__ void __launch_bounds__(256) wsplit4_kernel(
    const float* __restrict__ W0, const float* __restrict__ W1,
    const float* __restrict__ W2, const float* __restrict__ W3)
{
    __shared__ float t[32][33];
    const int z = blockIdx.z;
    const float* W = (z == 0) ? W0 : (z == 1) ? W1 : (z == 2) ? W2 : W3;
    __nv_bfloat16* Wht = g_Wht + (size_t)z * DD * DD;
    __nv_bfloat16* Wlt = g_Wlt + (size_t)z * DD * DD;

    int tx = threadIdx.x, ty = threadIdx.y;
    int n0 = blockIdx.x * 32, k0 = blockIdx.y * 32;
#pragma unroll
    for (int i = 0; i < 4; i++)
        t[ty + i * 8][tx] = W[(size_t)(k0 + ty + i * 8) * DD + n0 + tx];
    __syncthreads();
#pragma unroll
    for (int i = 0; i < 4; i++) {
        float v = t[tx][ty + i * 8];
        __nv_bfloat16 h = __float2bfloat16_rn(v);
        __nv_bfloat16 l = __float2bfloat16_rn(v - __bfloat162float(h));
        size_t idx = (size_t)(n0 + ty + i * 8) * DD + k0 + tx;
        Wht[idx] = h;
        Wlt[idx] = l;
    }
}

// ---------------------------------------------------------------------------
// GEMM mainloop (64x128 CTA tile, 128 threads, KC=32, double-buffered)
// ---------------------------------------------------------------------------
#define KC 32
#define GSTRIDE 40
#define TILE_A (64 * GSTRIDE * 2)
#define TILE_BB (128 * GSTRIDE * 2)
#define BUF_B  (2 * TILE_A + 2 * TILE_BB)
#define GEMM_SMEM (2 * BUF_B)

__device__ __forceinline__ void gemm_mainloop(
    uint32_t smem_u, int tid, int lane, int wm, int wn,
    const __nv_bfloat16* ah_g, const __nv_bfloat16* al_g,
    const __nv_bfloat16* bh_g, const __nv_bfloat16* bl_g,
    float acc[2][8][4])
{
    auto issue_chunk = [&](int c) {
        const uint32_t boff = smem_u + (uint32_t)(c & 1) * BUF_B;
#pragma unroll
        for (int i = 0; i < 4; i++) {
            int seg = tid + i * 128;
            int t = seg >> 8;
            int rem = seg & 255;
            int row = rem >> 2, g = rem & 3;
            const __nv_bfloat16* src = t ? al_g : ah_g;
            cp_async16(boff + (uint32_t)t * TILE_A
                       + (uint32_t)(row * GSTRIDE + g * 8) * 2,
                       src + (size_t)row * DD + c * KC + g * 8);
        }
#pragma unroll
        for (int i = 0; i < 8; i++) {
            int seg = tid + i * 128;
            int t = seg >> 9;
            int rem = seg & 511;
            int row = rem >> 2, g = rem & 3;
            const __nv_bfloat16* src = t ? bl_g : bh_g;
            cp_async16(boff + 2 * TILE_A + (uint32_t)t * TILE_BB
                       + (uint32_t)(row * GSTRIDE + g * 8) * 2,
                       src + (size_t)row * DD + c * KC + g * 8);
        }
    };

    const int a_row = wm * 32 + (lane & 15);
    const int a_kof = (lane >> 4) * 8;
    const int b_row = wn * 64 + (lane & 7) + (lane >> 4) * 8;
    const int b_kof = ((lane >> 3) & 1) * 8;

    issue_chunk(0);
    CP_COMMIT();

    for (int c = 0; c < 32; c++) {
        CP_WAIT0();
        __syncthreads();
        if (c < 31) { issue_chunk(c + 1); CP_COMMIT(); }

        const uint32_t boff = smem_u + (uint32_t)(c & 1) * BUF_B;
        const uint32_t tAh = boff;
        const uint32_t tAl = boff + TILE_A;
        const uint32_t tBh = boff + 2 * TILE_A;
        const uint32_t tBl = boff + 2 * TILE_A + TILE_BB;

#pragma unroll
        for (int kb = 0; kb < KC; kb += 16) {
            uint32_t ah[2][4], al[2][4], bh[8][2], bl[8][2];
#pragma unroll
            for (int mi = 0; mi < 2; mi++) {
                uint32_t ao = (uint32_t)((a_row + mi * 16) * GSTRIDE + kb + a_kof) * 2;
                ldsm_x4(ah[mi][0], ah[mi][1], ah[mi][2], ah[mi][3], tAh + ao);
                ldsm_x4(al[mi][0], al[mi][1], al[mi][2], al[mi][3], tAl + ao);
            }
#pragma unroll
            for (int p = 0; p < 4; p++) {
                uint32_t bo = (uint32_t)((p * 16 + b_row) * GSTRIDE + kb + b_kof) * 2;
                ldsm_x4(bh[2 * p][0], bh[2 * p][1], bh[2 * p + 1][0], bh[2 * p + 1][1], tBh + bo);
                ldsm_x4(bl[2 * p][0], bl[2 * p][1], bl[2 * p + 1][0], bl[2 * p + 1][1], tBl + bo);
            }
#pragma unroll
            for (int mi = 0; mi < 2; mi++)
#pragma unroll
                for (int ni = 0; ni < 8; ni++)
                    mma16816(acc[mi][ni], ah[mi], bh[ni]);   // hh
#pragma unroll
            for (int mi = 0; mi < 2; mi++)
#pragma unroll
                for (int ni = 0; ni < 8; ni++)
                    mma16816(acc[mi][ni], ah[mi], bl[ni]);   // hl
#pragma unroll
            for (int mi = 0; mi < 2; mi++)
#pragma unroll
                for (int ni = 0; ni < 8; ni++)
                    mma16816(acc[mi][ni], al[mi], bh[ni]);   // lh
        }
        __syncthreads();
    }
}

// ---------------------------------------------------------------------------
// Fused QKV projection GEMM. grid (8, 128, 3)
// ---------------------------------------------------------------------------
#define QSCALE 0.18033688011112042f   // 0.125 * log2(e): scores in log2 domain

__global__ void __launch_bounds__(128, 3) gemm_qkv_kernel(
    const float* __restrict__ bq, const float* __restrict__ bk,
    const float* __restrict__ bv)
{
    extern __shared__ char smem[];
    const uint32_t smem_u = smem_to_u32(smem);

    const int tid = threadIdx.x, wid = tid >> 5, lane = tid & 31;
    const int mtile = blockIdx.y, ntile = blockIdx.x, z = blockIdx.z;
    const int wm = wid & 1, wn = wid >> 1;

    const __nv_bfloat16* Bh_g = g_Wht + (size_t)z * DD * DD;
    const __nv_bfloat16* Bl_g = g_Wlt + (size_t)z * DD * DD;
    const float* bias = (z == 0) ? bq : (z == 1) ? bk : bv;
    __nv_bfloat16* Ch = (z == 0) ? g_Qh : (z == 1) ? g_Kh : g_Vh;
    __nv_bfloat16* Cl = (z == 0) ? g_Ql : (z == 1) ? g_Kl : g_Vl;
    const float scale = (z == 0) ? QSCALE : 1.0f;

    float acc[2][8][4];
#pragma unroll
    for (int mi = 0; mi < 2; mi++)
#pragma unroll
        for (int ni = 0; ni < 8; ni++)
#pragma unroll
            for (int r = 0; r < 4; r++) acc[mi][ni][r] = 0.0f;

    gemm_mainloop(smem_u, tid, lane, wm, wn,
                  g_Xh + (size_t)mtile * 64 * DD,
                  g_Xl + (size_t)mtile * 64 * DD,
                  Bh_g + (size_t)ntile * 128 * DD,
                  Bl_g + (size_t)ntile * 128 * DD, acc);

    const int mb = mtile * 64 + wm * 32 + (lane >> 2);
    const int nb0 = ntile * 128 + wn * 64 + (lane & 3) * 2;

#pragma unroll
    for (int mi = 0; mi < 2; mi++)
#pragma unroll
        for (int ni = 0; ni < 8; ni++) {
            int n = nb0 + ni * 8;
            float2 bsv = *(const float2*)(bias + n);
            int hh2 = n >> 6, hd = n & 63;
#pragma unroll
            for (int half = 0; half < 2; half++) {
                int mg = mb + mi * 16 + half * 8;
                float v0 = (acc[mi][ni][half * 2 + 0] + bsv.x) * scale;
                float v1 = (acc[mi][ni][half * 2 + 1] + bsv.y) * scale;
                __nv_bfloat162 hp = __floats2bfloat162_rn(v0, v1);
                __nv_bfloat162 lp = __floats2bfloat162_rn(
                    v0 - __bfloat162float(hp.x), v1 - __bfloat162float(hp.y));
                int bq2 = mg >> 12, sseq = mg & 4095;
                size_t off = ((size_t)(bq2 * HH + hh2) * SS + sseq) * HD + hd;
                *(__nv_bfloat162*)(Ch + off) = hp;
                *(__nv_bfloat162*)(Cl + off) = lp;
            }
        }
}

// ---------------------------------------------------------------------------
// Output projection GEMM. grid (8, 128)
// ---------------------------------------------------------------------------
__global__ void __launch_bounds__(128, 3) gemm_out_kernel(
    const float* __restrict__ bo, float* __restrict__ Cf)
{
    extern __shared__ char smem[];
    const uint32_t smem_u = smem_to_u32(smem);

    const int tid = threadIdx.x, wid = tid >> 5, lane = tid & 31;
    const int mtile = blockIdx.y, ntile = blockIdx.x;
    const int wm = wid & 1, wn = wid >> 1;

    float acc[2][8][4];
#pragma unroll
    for (int mi = 0; mi < 2; mi++)
#pragma unroll
        for (int ni = 0; ni < 8; ni++)
#pragma unroll
            for (int r = 0; r < 4; r++) acc[mi][ni][r] = 0.0f;

    gemm_mainloop(smem_u, tid, lane, wm, wn,
                  g_Ah + (size_t)mtile * 64 * DD,
                  g_Al + (size_t)mtile * 64 * DD,
                  g_Wht + 3 * (size_t)DD * DD + (size_t)ntile * 128 * DD,
                  g_Wlt + 3 * (size_t)DD * DD + (size_t)ntile * 128 * DD, acc);

    const int mb = mtile * 64 + wm * 32 + (lane >> 2);
    const int nb0 = ntile * 128 + wn * 64 + (lane & 3) * 2;

#pragma unroll
    for (int mi = 0; mi < 2; mi++)
#pragma unroll
        for (int ni = 0; ni < 8; ni++) {
            int n = nb0 + ni * 8;
            float2 bsv = *(const float2*)(bo + n);
#pragma unroll
            for (int half = 0; half < 2; half++) {
                int m = mb + mi * 16 + half * 8;
                float2 o;
                o.x = acc[mi][ni][half * 2 + 0] + bsv.x;
                o.y = acc[mi][ni][half * 2 + 1] + bsv.y;
                *(float2*)(Cf + (size_t)m * DD + n) = o;
            }
        }
}

// ---------------------------------------------------------------------------
// Flash attention, TQ=64, 128 threads, 3 CTAs/SM (Q smem overlaid on KV ring).
// ---------------------------------------------------------------------------
#define TQ 64
#define TK 64
#define QST 72
#define QTILE_B (64 * QST * 2)     // 9216
#define KTILE_B (64 * QST * 2)     // 9216
#define ATTN_SMEM (2 * 4 * KTILE_B)  // 73728 — Q staged here temporarily

__global__ void __launch_bounds__(128, 3) attn_mma_kernel()
{
    extern __shared__ char smem[];
    const uint32_t smem_u = smem_to_u32(smem);
    const uint32_t sBuf = smem_u;

    const int tid = threadIdx.x, wid = tid >> 5, lane = tid & 31;
    const int b = blockIdx.z, h = blockIdx.y;
    const int q0 = blockIdx.x * TQ;
    const size_t bhoff = (size_t)(b * HH + h) * SS * HD;

    // ---- Stage Q (hi+lo) into the KV ring area, extract frags, then free ----
    {
        const __nv_bfloat16* qsrc[2] = { g_Qh + bhoff + (size_t)q0 * HD,
                                         g_Ql + bhoff + (size_t)q0 * HD };
#pragma unroll
        for (int i = 0; i < 8; i++) {
            int seg = tid + i * 128;
            int arr = seg >> 9, rem = seg & 511;
            int row = rem >> 3, g = rem & 7;
            cp_async16(smem_u + (uint32_t)arr * QTILE_B + (uint32_t)(row * QST + g * 8) * 2,
                       qsrc[arr] + (size_t)row * HD + g * 8);
        }
    }
    CP_COMMIT();
    CP_WAIT0();
    __syncthreads();

    uint32_t qh[4][4], ql[4][4];
    {
        const int a_row = wid * 16 + (lane & 15);
        const int a_kof = (lane >> 4) * 8;
#pragma unroll
        for (int k = 0; k < 4; k++) {
            uint32_t ao = (uint32_t)(a_row * QST + k * 16 + a_kof) * 2;
            ldsm_x4(qh[k][0], qh[k][1], qh[k][2], qh[k][3], smem_u + ao);
            ldsm_x4(ql[k][0], ql[k][1], ql[k][2], ql[k][3], smem_u + QTILE_B + ao);
        }
    }
    __syncthreads();   // all warps extracted Q before KV overwrites the region

    const __nv_bfloat16* kvsrc[4] = { g_Kh + bhoff, g_Kl + bhoff,
                                      g_Vh + bhoff, g_Vl + bhoff };
    auto issue_kv = [&](int t) {
        const uint32_t boff = sBuf + (uint32_t)(t & 1) * (4 * KTILE_B);
#pragma unroll
        for (int i = 0; i < 16; i++) {
            int seg = tid + i * 128;
            int arr = seg >> 9;
            int rem = seg & 511;
            int row = rem >> 3, g = rem & 7;
            cp_async16(boff + (uint32_t)arr * KTILE_B + (uint32_t)(row * QST + g * 8) * 2,
                       kvsrc[arr] + (size_t)(t * TK + row) * HD + g * 8);
        }
    };
    issue_kv(0); CP_COMMIT();

    float m0 = -1e30f, m1 = -1e30f, l0 = 0.0f, l1 = 0.0f;
    float o[8][4];
#pragma unroll
    for (int nb = 0; nb < 8; nb++)
#pragma unroll
        for (int r = 0; r < 4; r++) o[nb][r] = 0.0f;

    const int b_row = (lane & 7) + (lane >> 4) * 8;
    const int b_kof = ((lane >> 3) & 1) * 8;
    const int v_row = (lane & 15);
    const int v_col = (lane >> 4) * 8;

    for (int t = 0; t < SS / TK; t++) {
        CP_WAIT0();
        __syncthreads();
        if (t < SS / TK - 1) { issue_kv(t + 1); CP_COMMIT(); }

        const uint32_t boff = sBuf + (uint32_t)(t & 1) * (4 * KTILE_B);
        const uint32_t tKh = boff, tKl = boff + KTILE_B;
        const uint32_t tVh = boff + 2 * KTILE_B, tVl = boff + 3 * KTILE_B;

        // ---- S = Q K^T (3-term split, term-major issue) ----
        float s[8][4];
#pragma unroll
        for (int nb = 0; nb < 8; nb++)
#pragma unroll
            for (int r = 0; r < 4; r++) s[nb][r] = 0.0f;

#pragma unroll
        for (int k = 0; k < 4; k++) {
            uint32_t kh[8][2], kl[8][2];
#pragma unroll
            for (int p = 0; p < 4; p++) {
                uint32_t bo = (uint32_t)((p * 16 + b_row) * QST + k * 16 + b_kof) * 2;
                ldsm_x4(kh[2 * p][0], kh[2 * p][1], kh[2 * p + 1][0], kh[2 * p + 1][1], tKh + bo);
                ldsm_x4(kl[2 * p][0], kl[2 * p][1], kl[2 * p + 1][0], kl[2 * p + 1][1], tKl + bo);
            }
#pragma unroll
            for (int nb = 0; nb < 8; nb++)
                mma16816(s[nb], qh[k], kh[nb]);   // hh
#pragma unroll
            for (int nb = 0; nb < 8; nb++)
                mma16816(s[nb], qh[k], kl[nb]);   // hl
#pragma unroll
            for (int nb = 0; nb < 8; nb++)
                mma16816(s[nb], ql[k], kh[nb]);   // lh
        }

        // ---- online softmax (log2 domain; scores carry log2e factor) ----
        float rm0 = -1e30f, rm1 = -1e30f;
#pragma unroll
        for (int nb = 0; nb < 8; nb++) {
            rm0 = fmaxf(rm0, fmaxf(s[nb][0], s[nb][1]));
            rm1 = fmaxf(rm1, fmaxf(s[nb][2], s[nb][3]));
        }
        rm0 = fmaxf(rm0, __shfl_xor_sync(0xffffffffu, rm0, 1));
        rm0 = fmaxf(rm0, __shfl_xor_sync(0xffffffffu, rm0, 2));
        rm1 = fmaxf(rm1, __shfl_xor_sync(0xffffffffu, rm1, 1));
        rm1 = fmaxf(rm1, __shfl_xor_sync(0xffffffffu, rm1, 2));

        float mn0 = fmaxf(m0, rm0), mn1 = fmaxf(m1, rm1);
        float al0 = ex2(m0 - mn0), al1 = ex2(m1 - mn1);
        m0 = mn0; m1 = mn1;

        float rs0 = 0.0f, rs1 = 0.0f;
#pragma unroll
        for (int nb = 0; nb < 8; nb++) {
            s[nb][0] = ex2(s[nb][0] - mn0);
            s[nb][1] = ex2(s[nb][1] - mn0);
            s[nb][2] = ex2(s[nb][2] - mn1);
            s[nb][3] = ex2(s[nb][3] - mn1);
            rs0 += s[nb][0] + s[nb][1];
            rs1 += s[nb][2] + s[nb][3];
        }
        rs0 += __shfl_xor_sync(0xffffffffu, rs0, 1);
        rs0 += __shfl_xor_sync(0xffffffffu, rs0, 2);
        rs1 += __shfl_xor_sync(0xffffffffu, rs1, 1);
        rs1 += __shfl_xor_sync(0xffffffffu, rs1, 2);
        l0 = l0 * al0 + rs0;
        l1 = l1 * al1 + rs1;
#pragma unroll
        for (int nb = 0; nb < 8; nb++) {
            o[nb][0] *= al0; o[nb][1] *= al0;
            o[nb][2] *= al1; o[nb][3] *= al1;
        }

        // ---- O += P V (pack P per-j to limit register pressure) ----
#pragma unroll
        for (int j = 0; j < 4; j++) {
            uint32_t ph[4], pl[4];
            {
                float pv[4][2] = {
                    { s[2 * j][0],     s[2 * j][1]     },
                    { s[2 * j][2],     s[2 * j][3]     },
                    { s[2 * j + 1][0], s[2 * j + 1][1] },
                    { s[2 * j + 1][2], s[2 * j + 1][3] } };
#pragma unroll
                for (int r = 0; r < 4; r++) {
                    __nv_bfloat162 hp = __floats2bfloat162_rn(pv[r][0], pv[r][1]);
                    __nv_bfloat162 lp = __floats2bfloat162_rn(
                        pv[r][0] - __bfloat162float(hp.x),
                        pv[r][1] - __bfloat162float(hp.y));
                    ph[r] = *reinterpret_cast<uint32_t*>(&hp);
                    pl[r] = *reinterpret_cast<uint32_t*>(&lp);
                }
            }
            uint32_t vh[8][2], vl[8][2];
#pragma unroll
            for (int p = 0; p < 4; p++) {
                uint32_t vo = (uint32_t)((j * 16 + v_row) * QST + p * 16 + v_col) * 2;
                ldsm_x4t(vh[2 * p][0], vh[2 * p][1], vh[2 * p + 1][0], vh[2 * p + 1][1], tVh + vo);
                ldsm_x4t(vl[2 * p][0], vl[2 * p][1], vl[2 * p + 1][0], vl[2 * p + 1][1], tVl + vo);
            }
#pragma unroll
            for (int nb = 0; nb < 8; nb++)
                mma16816(o[nb], ph, vh[nb]);   // hh
#pragma unroll
            for (int nb = 0; nb < 8; nb++)
                mma16816(o[nb], ph, vl[nb]);   // hl
#pragma unroll
            for (int nb = 0; nb < 8; nb++)
                mma16816(o[nb], pl, vh[nb]);   // lh
        }
    }

    // ---- epilogue ----
    const float inv0 = 1.0f / l0, inv1 = 1.0f / l1;
    const int qrow = q0 + wid * 16 + (lane >> 2);
    const size_t mrow0 = (size_t)(b * SS + qrow);
    const size_t mrow1 = mrow0 + 8;
    const int colb = h * HD + (lane & 3) * 2;
#pragma unroll
    for (int nb = 0; nb < 8; nb++) {
        int col = colb + nb * 8;
        float x0 = o[nb][0] * inv0, x1 = o[nb][1] * inv0;
        float x2 = o[nb][2] * inv1, x3 = o[nb][3] * inv1;
        __nv_bfloat162 h0 = __floats2bfloat162_rn(x0, x1);
        __nv_bfloat162 g0 = __floats2bfloat162_rn(
            x0 - __bfloat162float(h0.x), x1 - __bfloat162float(h0.y));
        __nv_bfloat162 h1 = __floats2bfloat162_rn(x2, x3);
        __nv_bfloat162 g1 = __floats2bfloat162_rn(
            x2 - __bfloat162float(h1.x), x3 - __bfloat162float(h1.y));
        *(__nv_bfloat162*)(g_Ah + mrow0 * DD + col) = h0;
        *(__nv_bfloat162*)(g_Al + mrow0 * DD + col) = g0;
        *(__nv_bfloat162*)(g_Ah + mrow1 * DD + col) = h1;
        *(__nv_bfloat162*)(g_Al + mrow1 * DD + col) = g1;
    }
}

// ---------------------------------------------------------------------------
// Launch
// ---------------------------------------------------------------------------
extern "C" void kernel_launch(void* const* d_in, const int* in_sizes, int n_in,
                              void* d_out, int out_size)
{
    (void)in_sizes; (void)n_in; (void)out_size;
    const float* X  = (const float*)d_in[0];
    const float* Wq = (const float*)d_in[1];
    const float* bq = (const float*)d_in[2];
    const float* Wk = (const float*)d_in[3];
    const float* bk = (const float*)d_in[4];
    const float* Wv = (const float*)d_in[5];
    const float* bv = (const float*)d_in[6];
    const float* Wo = (const float*)d_in[7];
    const float* bo = (const float*)d_in[8];
    float* out = (float*)d_out;

    __nv_bfloat16* pXh;
    __nv_bfloat16* pXl;
    cudaGetSymbolAddress((void**)&pXh, g_Xh);
    cudaGetSymbolAddress((void**)&pXl, g_Xl);

    cudaFuncSetAttribute(gemm_qkv_kernel,
                         cudaFuncAttributeMaxDynamicSharedMemorySize, GEMM_SMEM);
    cudaFuncSetAttribute(gemm_out_kernel,
                         cudaFuncAttributeMaxDynamicSharedMemorySize, GEMM_SMEM);
    cudaFuncSetAttribute(attn_mma_kernel,
                         cudaFuncAttributeMaxDynamicSharedMemorySize, ATTN_SMEM);

    xsplit_kernel<<<MM * DD / 4 / 256, 256>>>(X, pXh, pXl);
    dim3 gW(32, 32, 4), bW(32, 8);
    wsplit4_kernel<<<gW, bW>>>(Wq, Wk, Wv, Wo);

    dim3 gQKV(DD / 128, MM / 64, 3);
    gemm_qkv_kernel<<<gQKV, 128, GEMM_SMEM>>>(bq, bk, bv);

    dim3 gattn(SS / TQ, HH, BB);
    attn_mma_kernel<<<gattn, 128, ATTN_SMEM>>>();

    dim3 gO(DD / 128, MM / 64);
    gemm_out_kernel<<<gO, 128, GEMM_SMEM>>>(bo, out);
}